// round 1
// baseline (speedup 1.0000x reference)
#include <cuda_runtime.h>
#include <cuda_bf16.h>
#include <math.h>

#define NQ 1024
#define NS 256
#define E  256
#define H1 256   // 4*R
#define H2 128   // 2*R
#define H3 64    // R
#define TQ 64    // query rows per CTA

// Scratch (statically declared — no runtime allocation)
__device__ float g_QpT[H1 * NQ];   // [k][q]  : Qp transposed for coalesced tile loads
__device__ float g_Sp [NS * H1];   // [s][k]  : Sp row-major (+b1 folded in)

__device__ __forceinline__ float frelu(float x) { return fmaxf(x, 0.0f); }

// ---------------------------------------------------------------------------
// Precompute: Qp = qf @ W1[0:E]  (no bias),  Sp = sf @ W1[E:2E] + b1
// 80 CTAs x 256 threads. CTA handles 16 rows; thread j owns output column j.
// ---------------------------------------------------------------------------
__global__ void precompute_kernel(const float* __restrict__ qf,
                                  const float* __restrict__ sf,
                                  const float* __restrict__ W1,
                                  const float* __restrict__ b1)
{
    const int blk  = blockIdx.x;          // 0..63 -> Qp, 64..79 -> Sp
    const bool isQ = (blk < 64);
    const int row0 = isQ ? blk * 16 : (blk - 64) * 16;
    const float* feat = isQ ? qf : sf;
    const int woff = isQ ? 0 : E;

    __shared__ float sF[16][E];
    const int tid = threadIdx.x;          // 256

    #pragma unroll
    for (int r = 0; r < 16; r++)
        sF[r][tid] = feat[(row0 + r) * E + tid];
    __syncthreads();

    const int j = tid;
    float acc[16];
    #pragma unroll
    for (int r = 0; r < 16; r++) acc[r] = 0.0f;

    for (int k = 0; k < E; k++) {
        const float w = W1[(woff + k) * H1 + j];
        #pragma unroll
        for (int r = 0; r < 16; r++) acc[r] += sF[r][k] * w;
    }

    if (isQ) {
        #pragma unroll
        for (int r = 0; r < 16; r++)
            g_QpT[j * NQ + row0 + r] = acc[r];
    } else {
        const float bb = b1[j];
        #pragma unroll
        for (int r = 0; r < 16; r++)
            g_Sp[(row0 + r) * H1 + j] = acc[r] + bb;
    }
}

// ---------------------------------------------------------------------------
// Main fused kernel: one CTA = (64 query rows) x (1 support col) = 64 pairs.
//   h1 tile built on the fly:  relu(QpT[k][q] + Sp[s][k])
//   layer2: [64,256]@[256,128]  register-tiled 4x8 per thread (16x16 threads)
//   layer3: [64,128]@[128, 64]  register-tiled 4x4 per thread
//   layer4: dot-64 + sigmoid, 4 lanes per pair + shfl reduce
// ---------------------------------------------------------------------------
struct SmemMain {
    float sSp[H1];            // Sp row for this CTA's support index
    float As[16][TQ];         // h1 k-chunk, transposed [kk][r]
    float Bs[16][H2];         // W2 k-chunk [kk][j]
    float h2T[H2][TQ + 4];    // layer2 output transposed [col][row], padded
    float W3s[H2 * H3];       // whole W3
    float h3s[TQ][H3 + 4];    // layer3 output [row][col], padded
    float sW4[H3];
};

__global__ void __launch_bounds__(256, 2)
relation_main_kernel(const float* __restrict__ W2,
                     const float* __restrict__ b2,
                     const float* __restrict__ W3,
                     const float* __restrict__ b3,
                     const float* __restrict__ W4,
                     const float* __restrict__ b4,
                     float* __restrict__ out)
{
    extern __shared__ char smem_raw[];
    SmemMain& sm = *reinterpret_cast<SmemMain*>(smem_raw);

    const int s_idx = blockIdx.x;          // 0..255
    const int q0    = blockIdx.y * TQ;     // 0..960
    const int tid   = threadIdx.x;         // 256
    const int tr    = tid >> 4;            // 0..15 (row group)
    const int tc    = tid & 15;            // 0..15 (col group)

    // ---- prologue: stage Sp row, W3, W4 ----
    sm.sSp[tid] = g_Sp[s_idx * H1 + tid];
    {
        const float4* src = reinterpret_cast<const float4*>(W3);
        float4* dst = reinterpret_cast<float4*>(sm.W3s);
        #pragma unroll
        for (int i = 0; i < 8; i++) dst[tid + 256 * i] = src[tid + 256 * i];
    }
    if (tid < H3) sm.sW4[tid] = W4[tid];
    __syncthreads();

    // ---- layer2 mainloop ----
    float acc[4][8];
    #pragma unroll
    for (int r = 0; r < 4; r++)
        #pragma unroll
        for (int c = 0; c < 8; c++) acc[r][c] = 0.0f;

    const int fkk = tid >> 4;              // fill: k within chunk (0..15)
    const int fr0 = (tid & 15) * 4;        // fill: As rows
    const int fj0 = (tid & 15) * 8;        // fill: Bs cols

    for (int k0 = 0; k0 < H1; k0 += 16) {
        // build h1 chunk: As[kk][r] = relu(QpT[k0+kk][q0+r] + Sp[k0+kk])
        float4 qv = *reinterpret_cast<const float4*>(&g_QpT[(k0 + fkk) * NQ + q0 + fr0]);
        const float sp = sm.sSp[k0 + fkk];
        float4 av;
        av.x = frelu(qv.x + sp);
        av.y = frelu(qv.y + sp);
        av.z = frelu(qv.z + sp);
        av.w = frelu(qv.w + sp);
        *reinterpret_cast<float4*>(&sm.As[fkk][fr0]) = av;

        // stage W2 chunk
        float4 w0 = *reinterpret_cast<const float4*>(&W2[(k0 + fkk) * H2 + fj0]);
        float4 w1 = *reinterpret_cast<const float4*>(&W2[(k0 + fkk) * H2 + fj0 + 4]);
        *reinterpret_cast<float4*>(&sm.Bs[fkk][fj0])     = w0;
        *reinterpret_cast<float4*>(&sm.Bs[fkk][fj0 + 4]) = w1;
        __syncthreads();

        #pragma unroll
        for (int kk = 0; kk < 16; kk++) {
            float4 a  = *reinterpret_cast<const float4*>(&sm.As[kk][tr * 4]);
            float4 b0 = *reinterpret_cast<const float4*>(&sm.Bs[kk][tc * 4]);
            float4 b1v= *reinterpret_cast<const float4*>(&sm.Bs[kk][64 + tc * 4]);
            const float aa[4] = {a.x, a.y, a.z, a.w};
            const float bb[8] = {b0.x, b0.y, b0.z, b0.w, b1v.x, b1v.y, b1v.z, b1v.w};
            #pragma unroll
            for (int r = 0; r < 4; r++)
                #pragma unroll
                for (int c = 0; c < 8; c++)
                    acc[r][c] += aa[r] * bb[c];
        }
        __syncthreads();
    }

    // ---- layer2 epilogue: bias + relu -> h2T[col][row] ----
    #pragma unroll
    for (int c = 0; c < 8; c++) {
        const int col = (c < 4) ? (tc * 4 + c) : (64 + tc * 4 + (c - 4));
        const float bias = b2[col];
        #pragma unroll
        for (int r = 0; r < 4; r++)
            sm.h2T[col][tr * 4 + r] = frelu(acc[r][c] + bias);
    }
    __syncthreads();

    // ---- layer3: [64,128] @ [128,64] ----
    float acc3[4][4];
    #pragma unroll
    for (int r = 0; r < 4; r++)
        #pragma unroll
        for (int c = 0; c < 4; c++) acc3[r][c] = 0.0f;

    #pragma unroll 8
    for (int kk = 0; kk < H2; kk++) {
        float4 a = *reinterpret_cast<const float4*>(&sm.h2T[kk][tr * 4]);
        float4 b = *reinterpret_cast<const float4*>(&sm.W3s[kk * H3 + tc * 4]);
        const float aa[4] = {a.x, a.y, a.z, a.w};
        const float bb[4] = {b.x, b.y, b.z, b.w};
        #pragma unroll
        for (int r = 0; r < 4; r++)
            #pragma unroll
            for (int c = 0; c < 4; c++)
                acc3[r][c] += aa[r] * bb[c];
    }

    // layer3 epilogue: bias + relu -> h3s[row][col]
    {
        const float bx = b3[tc * 4 + 0];
        const float by = b3[tc * 4 + 1];
        const float bz = b3[tc * 4 + 2];
        const float bw = b3[tc * 4 + 3];
        #pragma unroll
        for (int r = 0; r < 4; r++) {
            float4 v;
            v.x = frelu(acc3[r][0] + bx);
            v.y = frelu(acc3[r][1] + by);
            v.z = frelu(acc3[r][2] + bz);
            v.w = frelu(acc3[r][3] + bw);
            *reinterpret_cast<float4*>(&sm.h3s[tr * 4 + r][tc * 4]) = v;
        }
    }
    __syncthreads();

    // ---- layer4: dot(h3, W4) + b4, sigmoid ----
    const int p = tid >> 2;                // pair 0..63
    const int l = tid & 3;                 // lane within quad
    float sum = 0.0f;
    #pragma unroll
    for (int i = 0; i < 16; i++) {
        const int c = l * 16 + i;
        sum += sm.h3s[p][c] * sm.sW4[c];
    }
    sum += __shfl_xor_sync(0xffffffffu, sum, 1);
    sum += __shfl_xor_sync(0xffffffffu, sum, 2);
    if (l == 0) {
        const float v = sum + b4[0];
        out[(q0 + p) * NS + s_idx] = 1.0f / (1.0f + expf(-v));
    }
}

// ---------------------------------------------------------------------------
extern "C" void kernel_launch(void* const* d_in, const int* in_sizes, int n_in,
                              void* d_out, int out_size)
{
    const float* qf = (const float*)d_in[0];
    const float* sf = (const float*)d_in[1];
    // d_in[2] = support_y (unused by the reference computation)
    const float* W1 = (const float*)d_in[3];
    const float* b1 = (const float*)d_in[4];
    const float* W2 = (const float*)d_in[5];
    const float* b2 = (const float*)d_in[6];
    const float* W3 = (const float*)d_in[7];
    const float* b3 = (const float*)d_in[8];
    const float* W4 = (const float*)d_in[9];
    const float* b4 = (const float*)d_in[10];
    float* out = (float*)d_out;

    cudaFuncSetAttribute(relation_main_kernel,
                         cudaFuncAttributeMaxDynamicSharedMemorySize,
                         (int)sizeof(SmemMain));

    precompute_kernel<<<80, 256>>>(qf, sf, W1, b1);
    relation_main_kernel<<<dim3(NS, NQ / TQ), 256, sizeof(SmemMain)>>>(
        W2, b2, W3, b3, W4, b4, out);
}

// round 4
// speedup vs baseline: 2.3359x; 2.3359x over previous
#include <cuda_runtime.h>
#include <cuda_bf16.h>
#include <math.h>
#include <stdint.h>

#define NQ 1024
#define NS 256
#define E  256
#define H1 256
#define H2 128
#define H3 64
#define TM 128          // query rows per CTA

// ---------------- warp-MMA helpers (plain sm_80+ PTX, no 'a' target) --------
__device__ __forceinline__ uint32_t smem_to_u32(const void* p) {
    uint32_t a;
    asm("{ .reg .u64 t; cvta.to.shared.u64 t, %1; cvt.u32.u64 %0, t; }" : "=r"(a) : "l"(p));
    return a;
}
__device__ __forceinline__ void ldsm4(uint32_t* r, uint32_t addr) {
    asm volatile("ldmatrix.sync.aligned.m8n8.x4.shared.b16 {%0,%1,%2,%3}, [%4];"
                 : "=r"(r[0]), "=r"(r[1]), "=r"(r[2]), "=r"(r[3]) : "r"(addr));
}
__device__ __forceinline__ void ldsm4t(uint32_t* r, uint32_t addr) {
    asm volatile("ldmatrix.sync.aligned.m8n8.x4.trans.shared.b16 {%0,%1,%2,%3}, [%4];"
                 : "=r"(r[0]), "=r"(r[1]), "=r"(r[2]), "=r"(r[3]) : "r"(addr));
}
__device__ __forceinline__ void mma_bf16(float* d, const uint32_t* a, const uint32_t* b) {
    asm volatile("mma.sync.aligned.m16n8k16.row.col.f32.bf16.bf16.f32 "
                 "{%0,%1,%2,%3}, {%4,%5,%6,%7}, {%8,%9}, {%0,%1,%2,%3};"
                 : "+f"(d[0]), "+f"(d[1]), "+f"(d[2]), "+f"(d[3])
                 : "r"(a[0]), "r"(a[1]), "r"(a[2]), "r"(a[3]), "r"(b[0]), "r"(b[1]));
}
__device__ __forceinline__ void split_bf16(float x, __nv_bfloat16& hi, __nv_bfloat16& lo) {
    hi = __float2bfloat16_rn(x);
    lo = __float2bfloat16_rn(x - __bfloat162float(hi));
}
__device__ __forceinline__ uint32_t pack2(__nv_bfloat16 a, __nv_bfloat16 b) {
    __nv_bfloat162 t; t.x = a; t.y = b;
    return *reinterpret_cast<uint32_t*>(&t);
}
__device__ __forceinline__ float frelu(float x) { return fmaxf(x, 0.0f); }

// ---------------- global scratch (static) -----------------------------------
__device__ float g_QpT[H1 * NQ];                  // [k][q]
__device__ float g_Sp [NS * H1];                  // [s][k] (+b1)
__device__ __nv_bfloat16 g_W2TB_hi[8][5120];      // [chunk][n*40 + kk], kk<32 data
__device__ __nv_bfloat16 g_W2TB_lo[8][5120];
__device__ __nv_bfloat16 g_W3TB_hi[8704];         // [n*136 + k], k<128 data
__device__ __nv_bfloat16 g_W3TB_lo[8704];

// ---------------- smem layout (bytes) ---------------------------------------
#define SM_ATH 0          // h1^T hi  [32k][136m] bf16 = 8704
#define SM_ATL 8704       // h1^T lo
#define SM_B2H 17408      // W2^T chunk hi [128n][40k] = 10240
#define SM_B2L 27648
// aliases after layer2 mainloop:
#define SM_W3H 0          // W3^T hi [64n][136k] = 17408
#define SM_W3L 17408
#define SM_H2H 37888      // h2 hi [128m][136k] = 34816
#define SM_H2L 72704
#define SM_SSP 107520     // 256 f32
#define SM_B2S 108544     // 128 f32
#define SM_B3S 109056     // 64 f32
#define SM_W4S 109312     // 64 f32
#define SM_RED 109568     // 2*128 f32
#define SMEM_TOTAL 110592

// ---------------------------------------------------------------------------
__global__ void precompute_kernel(const float* __restrict__ qf,
                                  const float* __restrict__ sf,
                                  const float* __restrict__ W1,
                                  const float* __restrict__ b1)
{
    const int blk  = blockIdx.x;
    const bool isQ = (blk < 64);
    const int row0 = isQ ? blk * 16 : (blk - 64) * 16;
    const float* feat = isQ ? qf : sf;
    const int woff = isQ ? 0 : E;

    __shared__ float sF[16][E];
    const int tid = threadIdx.x;
    #pragma unroll
    for (int r = 0; r < 16; r++) sF[r][tid] = feat[(row0 + r) * E + tid];
    __syncthreads();

    const int j = tid;
    float acc[16];
    #pragma unroll
    for (int r = 0; r < 16; r++) acc[r] = 0.0f;
    for (int k = 0; k < E; k++) {
        const float w = W1[(woff + k) * H1 + j];
        #pragma unroll
        for (int r = 0; r < 16; r++) acc[r] += sF[r][k] * w;
    }
    if (isQ) {
        #pragma unroll
        for (int r = 0; r < 16; r++) g_QpT[j * NQ + row0 + r] = acc[r];
    } else {
        const float bb = b1[j];
        #pragma unroll
        for (int r = 0; r < 16; r++) g_Sp[(row0 + r) * H1 + j] = acc[r] + bb;
    }
}

// Pre-split + pad weights into mma-friendly layouts.
// FIXED (R3 bug): W2 clause is now bounded to 8*5120 entries — previously
// threads t>=40960 wrote g_W2TB_hi[c>=8][...] which overran into the lo/W3
// tables (racy garbage in all lo-correction terms -> rel_err 9e-3).
__global__ void prep_weights_kernel(const float* __restrict__ W2,
                                    const float* __restrict__ W3)
{
    const int t = blockIdx.x * blockDim.x + threadIdx.x;   // 160*256 = 40960
    if (t < 8 * 5120) {
        const int c = t / 5120, r = t % 5120;
        const int n = r / 40, kk = r % 40;
        const float w = (kk < 32) ? W2[(c * 32 + kk) * H2 + n] : 0.0f;
        __nv_bfloat16 hi, lo; split_bf16(w, hi, lo);
        g_W2TB_hi[c][r] = hi;
        g_W2TB_lo[c][r] = lo;
    }
    if (t < 8704) {
        const int n = t / 136, k = t % 136;
        const float w = (k < 128) ? W3[k * H3 + n] : 0.0f;
        __nv_bfloat16 hi, lo; split_bf16(w, hi, lo);
        g_W3TB_hi[t] = hi;
        g_W3TB_lo[t] = lo;
    }
}

// ---------------------------------------------------------------------------
// Fused MLP: one CTA = 128 q-pairs x 1 support; layers 2..4 via mma.sync bf16
// ---------------------------------------------------------------------------
__global__ void __launch_bounds__(256, 2)
relation_mma_kernel(const float* __restrict__ b2,
                    const float* __restrict__ b3,
                    const float* __restrict__ W4,
                    const float* __restrict__ b4,
                    float* __restrict__ out)
{
    extern __shared__ char smem[];
    const uint32_t sb = smem_to_u32(smem);
    const int tid  = threadIdx.x;
    const int lane = tid & 31;
    const int wid  = tid >> 5;
    const int wm   = wid & 3;          // 4 warps along M
    const int wn   = wid >> 2;         // 2 warps along N
    const int s_idx = blockIdx.x;
    const int q0    = blockIdx.y * TM;

    float* sSp = (float*)(smem + SM_SSP);
    float* b2s = (float*)(smem + SM_B2S);
    float* b3s = (float*)(smem + SM_B3S);
    float* W4s = (float*)(smem + SM_W4S);
    float* red = (float*)(smem + SM_RED);

    sSp[tid] = g_Sp[s_idx * H1 + tid];
    if (tid < H2) b2s[tid] = b2[tid];
    if (tid < H3) { b3s[tid] = b3[tid]; W4s[tid] = W4[tid]; }
    __syncthreads();

    float acc[2][8][4];
    #pragma unroll
    for (int a = 0; a < 2; a++)
        #pragma unroll
        for (int b = 0; b < 8; b++)
            #pragma unroll
            for (int c = 0; c < 4; c++) acc[a][b][c] = 0.0f;

    const int kk = tid >> 3;           // 0..31 (build: k row within chunk)
    const int qo = (tid & 7) * 16;     // 0..112 (build: q offset)

    // =================== layer2 mainloop: 8 chunks of k=32 ==================
    for (int c = 0; c < 8; ++c) {
        if (c) __syncthreads();

        // stage W2^T chunk (pre-split, pre-padded): 640 float4 each
        {
            const float4* gh = reinterpret_cast<const float4*>(g_W2TB_hi[c]);
            const float4* gl = reinterpret_cast<const float4*>(g_W2TB_lo[c]);
            float4* dh = reinterpret_cast<float4*>(smem + SM_B2H);
            float4* dl = reinterpret_cast<float4*>(smem + SM_B2L);
            #pragma unroll
            for (int i = 0; i < 3; ++i) {
                const int t = tid + 256 * i;
                if (t < 640) { dh[t] = gh[t]; dl[t] = gl[t]; }
            }
        }
        // build h1 chunk: relu(QpT + Sp) -> split -> AT[k][m] hi/lo
        {
            const float sp = sSp[c * 32 + kk];
            const float4* qp = reinterpret_cast<const float4*>(
                &g_QpT[(c * 32 + kk) * NQ + q0 + qo]);
            uint32_t* ath = reinterpret_cast<uint32_t*>(smem + SM_ATH);
            uint32_t* atl = reinterpret_cast<uint32_t*>(smem + SM_ATL);
            const int wbase = kk * 68 + (qo >> 1);
            #pragma unroll
            for (int v = 0; v < 4; ++v) {
                const float4 q4 = qp[v];
                const float x0 = frelu(q4.x + sp), x1 = frelu(q4.y + sp);
                const float x2 = frelu(q4.z + sp), x3 = frelu(q4.w + sp);
                __nv_bfloat16 h0,l0,h1v,l1,h2v,l2,h3v,l3;
                split_bf16(x0,h0,l0); split_bf16(x1,h1v,l1);
                split_bf16(x2,h2v,l2); split_bf16(x3,h3v,l3);
                ath[wbase + 2*v    ] = pack2(h0, h1v);
                ath[wbase + 2*v + 1] = pack2(h2v, h3v);
                atl[wbase + 2*v    ] = pack2(l0, l1);
                atl[wbase + 2*v + 1] = pack2(l2, l3);
            }
        }
        __syncthreads();

        // mma phase
        #pragma unroll
        for (int ks = 0; ks < 2; ++ks) {
            uint32_t ahi[2][4], alo[2][4];
            const int arow = ks * 16 + (lane & 7) + 8 * (lane >> 4);
            #pragma unroll
            for (int tm = 0; tm < 2; ++tm) {
                const int acol = wm * 32 + tm * 16 + 8 * ((lane >> 3) & 1);
                const uint32_t aaddr = sb + SM_ATH + arow * 272 + acol * 2;
                ldsm4t(ahi[tm], aaddr);
                ldsm4t(alo[tm], aaddr + (SM_ATL - SM_ATH));
            }
            #pragma unroll
            for (int tp = 0; tp < 4; ++tp) {
                uint32_t bh[4], bl[4];
                const int nrow = wn * 64 + tp * 16 + (lane & 7) + 8 * (lane >> 4);
                const int kcol = ks * 16 + 8 * ((lane >> 3) & 1);
                const uint32_t baddr = sb + SM_B2H + nrow * 80 + kcol * 2;
                ldsm4(bh, baddr);
                ldsm4(bl, baddr + (SM_B2L - SM_B2H));
                #pragma unroll
                for (int tm = 0; tm < 2; ++tm) {
                    mma_bf16(acc[tm][2*tp    ], ahi[tm], &bh[0]);
                    mma_bf16(acc[tm][2*tp    ], ahi[tm], &bl[0]);
                    mma_bf16(acc[tm][2*tp    ], alo[tm], &bh[0]);
                    mma_bf16(acc[tm][2*tp + 1], ahi[tm], &bh[2]);
                    mma_bf16(acc[tm][2*tp + 1], ahi[tm], &bl[2]);
                    mma_bf16(acc[tm][2*tp + 1], alo[tm], &bh[2]);
                }
            }
        }
    }
    __syncthreads();   // staging free; h2/W3 regions safe to write

    // stage whole W3^T (aliases layer2 staging): 1088 float4 each
    {
        const float4* gh = reinterpret_cast<const float4*>(g_W3TB_hi);
        const float4* gl = reinterpret_cast<const float4*>(g_W3TB_lo);
        float4* dh = reinterpret_cast<float4*>(smem + SM_W3H);
        float4* dl = reinterpret_cast<float4*>(smem + SM_W3L);
        #pragma unroll
        for (int i = 0; i < 5; ++i) {
            const int t = tid + 256 * i;
            if (t < 1088) { dh[t] = gh[t]; dl[t] = gl[t]; }
        }
    }
    // layer2 epilogue: bias+relu -> split -> h2[m][k] hi/lo (packed u32 stores)
    {
        uint32_t* hh = reinterpret_cast<uint32_t*>(smem + SM_H2H);
        uint32_t* hl = reinterpret_cast<uint32_t*>(smem + SM_H2L);
        #pragma unroll
        for (int tm = 0; tm < 2; ++tm) {
            #pragma unroll
            for (int tn = 0; tn < 8; ++tn) {
                const int n = wn * 64 + tn * 8 + (lane & 3) * 2;
                const int m = wm * 32 + tm * 16 + (lane >> 2);
                const float bn0 = b2s[n], bn1 = b2s[n + 1];
                #pragma unroll
                for (int rr = 0; rr < 2; ++rr) {
                    const float x0 = frelu(acc[tm][tn][2*rr    ] + bn0);
                    const float x1 = frelu(acc[tm][tn][2*rr + 1] + bn1);
                    __nv_bfloat16 h0,l0,h1v,l1;
                    split_bf16(x0,h0,l0); split_bf16(x1,h1v,l1);
                    const int w = (m + 8*rr) * 68 + (n >> 1);
                    hh[w] = pack2(h0, h1v);
                    hl[w] = pack2(l0, l1);
                }
            }
        }
    }
    __syncthreads();

    // =================== layer3: h2[128x128] @ W3[128x64] ===================
    float acc3[2][4][4];
    #pragma unroll
    for (int a = 0; a < 2; a++)
        #pragma unroll
        for (int b = 0; b < 4; b++)
            #pragma unroll
            for (int c = 0; c < 4; c++) acc3[a][b][c] = 0.0f;

    #pragma unroll
    for (int ks = 0; ks < 8; ++ks) {
        uint32_t ahi[2][4], alo[2][4];
        #pragma unroll
        for (int tm = 0; tm < 2; ++tm) {
            const int mrow = wm * 32 + tm * 16 + (lane & 7) + 8 * ((lane >> 3) & 1);
            const int kcol = ks * 16 + 8 * (lane >> 4);
            const uint32_t aaddr = sb + SM_H2H + mrow * 272 + kcol * 2;
            ldsm4(ahi[tm], aaddr);
            ldsm4(alo[tm], aaddr + (SM_H2L - SM_H2H));
        }
        #pragma unroll
        for (int tp = 0; tp < 2; ++tp) {
            uint32_t bh[4], bl[4];
            const int nrow = wn * 32 + tp * 16 + (lane & 7) + 8 * (lane >> 4);
            const int kcol = ks * 16 + 8 * ((lane >> 3) & 1);
            const uint32_t baddr = sb + SM_W3H + nrow * 272 + kcol * 2;
            ldsm4(bh, baddr);
            ldsm4(bl, baddr + (SM_W3L - SM_W3H));
            #pragma unroll
            for (int tm = 0; tm < 2; ++tm) {
                mma_bf16(acc3[tm][2*tp    ], ahi[tm], &bh[0]);
                mma_bf16(acc3[tm][2*tp    ], ahi[tm], &bl[0]);
                mma_bf16(acc3[tm][2*tp    ], alo[tm], &bh[0]);
                mma_bf16(acc3[tm][2*tp + 1], ahi[tm], &bh[2]);
                mma_bf16(acc3[tm][2*tp + 1], ahi[tm], &bl[2]);
                mma_bf16(acc3[tm][2*tp + 1], alo[tm], &bh[2]);
            }
        }
    }

    // ============== layer3 epilogue + layer4 (registers + shfl) =============
    float part[4] = {0.0f, 0.0f, 0.0f, 0.0f};   // rows: tm*16 + rr*8 + (lane>>2)
    #pragma unroll
    for (int tn = 0; tn < 4; ++tn) {
        const int n = wn * 32 + tn * 8 + (lane & 3) * 2;
        const float bn0 = b3s[n], bn1 = b3s[n + 1];
        const float w0 = W4s[n],  w1 = W4s[n + 1];
        #pragma unroll
        for (int tm = 0; tm < 2; ++tm) {
            #pragma unroll
            for (int rr = 0; rr < 2; ++rr) {
                part[tm*2 + rr] += frelu(acc3[tm][tn][2*rr    ] + bn0) * w0
                                 + frelu(acc3[tm][tn][2*rr + 1] + bn1) * w1;
            }
        }
    }
    #pragma unroll
    for (int i = 0; i < 4; ++i) {
        part[i] += __shfl_xor_sync(0xffffffffu, part[i], 1);
        part[i] += __shfl_xor_sync(0xffffffffu, part[i], 2);
    }
    if ((lane & 3) == 0) {
        #pragma unroll
        for (int tm = 0; tm < 2; ++tm)
            #pragma unroll
            for (int rr = 0; rr < 2; ++rr) {
                const int m = wm * 32 + tm * 16 + rr * 8 + (lane >> 2);
                red[wn * 128 + m] = part[tm*2 + rr];
            }
    }
    __syncthreads();
    if (tid < 128) {
        const float v = red[tid] + red[128 + tid] + b4[0];
        out[(q0 + tid) * NS + s_idx] = 1.0f / (1.0f + expf(-v));
    }
}

// ---------------------------------------------------------------------------
extern "C" void kernel_launch(void* const* d_in, const int* in_sizes, int n_in,
                              void* d_out, int out_size)
{
    const float* qf = (const float*)d_in[0];
    const float* sf = (const float*)d_in[1];
    // d_in[2] = support_y (unused)
    const float* W1 = (const float*)d_in[3];
    const float* b1 = (const float*)d_in[4];
    const float* W2 = (const float*)d_in[5];
    const float* b2 = (const float*)d_in[6];
    const float* W3 = (const float*)d_in[7];
    const float* b3 = (const float*)d_in[8];
    const float* W4 = (const float*)d_in[9];
    const float* b4 = (const float*)d_in[10];
    float* out = (float*)d_out;

    cudaFuncSetAttribute(relation_mma_kernel,
                         cudaFuncAttributeMaxDynamicSharedMemorySize, SMEM_TOTAL);

    precompute_kernel<<<80, 256>>>(qf, sf, W1, b1);
    prep_weights_kernel<<<160, 256>>>(W2, W3);
    relation_mma_kernel<<<dim3(NS, NQ / TM), 256, SMEM_TOTAL>>>(b2, b3, W4, b4, out);
}

// round 5
// speedup vs baseline: 3.1539x; 1.3502x over previous
#include <cuda_runtime.h>
#include <cuda_fp16.h>
#include <math.h>
#include <stdint.h>

#define NQ 1024
#define NS 256
#define E  256
#define H1 256
#define H2 128
#define H3 64
#define TM 128          // query rows per CTA

// ---------------- warp-MMA helpers (plain sm_80+ PTX) -----------------------
__device__ __forceinline__ uint32_t smem_to_u32(const void* p) {
    uint32_t a;
    asm("{ .reg .u64 t; cvta.to.shared.u64 t, %1; cvt.u32.u64 %0, t; }" : "=r"(a) : "l"(p));
    return a;
}
__device__ __forceinline__ void ldsm4(uint32_t* r, uint32_t addr) {
    asm volatile("ldmatrix.sync.aligned.m8n8.x4.shared.b16 {%0,%1,%2,%3}, [%4];"
                 : "=r"(r[0]), "=r"(r[1]), "=r"(r[2]), "=r"(r[3]) : "r"(addr));
}
__device__ __forceinline__ void ldsm4t(uint32_t* r, uint32_t addr) {
    asm volatile("ldmatrix.sync.aligned.m8n8.x4.trans.shared.b16 {%0,%1,%2,%3}, [%4];"
                 : "=r"(r[0]), "=r"(r[1]), "=r"(r[2]), "=r"(r[3]) : "r"(addr));
}
__device__ __forceinline__ void mma_f16(float* d, const uint32_t* a, const uint32_t* b) {
    asm volatile("mma.sync.aligned.m16n8k16.row.col.f32.f16.f16.f32 "
                 "{%0,%1,%2,%3}, {%4,%5,%6,%7}, {%8,%9}, {%0,%1,%2,%3};"
                 : "+f"(d[0]), "+f"(d[1]), "+f"(d[2]), "+f"(d[3])
                 : "r"(a[0]), "r"(a[1]), "r"(a[2]), "r"(a[3]), "r"(b[0]), "r"(b[1]));
}
__device__ __forceinline__ void split_f16(float x, __half& hi, __half& lo) {
    hi = __float2half_rn(x);
    lo = __float2half_rn(x - __half2float(hi));
}
__device__ __forceinline__ uint32_t pack2h(__half a, __half b) {
    __half2 t; t.x = a; t.y = b;
    return *reinterpret_cast<uint32_t*>(&t);
}
__device__ __forceinline__ float frelu(float x) { return fmaxf(x, 0.0f); }

// ---------------- global scratch (static) -----------------------------------
__device__ float g_QpT[H1 * NQ];              // [k][q]
__device__ float g_Sp [NS * H1];              // [s][k] (+b1)
__device__ __half g_W2TB_hi[8][5120];         // [chunk][n*40 + kk], kk<32 data
__device__ __half g_W2TB_lo[8][5120];
__device__ __half g_W3TB_hi[8704];            // [n*136 + k], k<128 data
__device__ __half g_W3TB_lo[8704];

// ---------------- smem layout (bytes) ---------------------------------------
#define SM_AT  0          // h1^T fp16  [32k][136m] = 8704
#define SM_B2H 8704       // W2^T chunk hi [128n][40k] = 10240
#define SM_B2L 18944      // lo (phase A ends 29184)
// aliases after layer2 mainloop:
#define SM_W3H 0          // W3^T hi [64n][136k] = 17408
#define SM_W3L 17408      // lo (ends 34816)
#define SM_H2  34816      // h2 fp16 [128m][136k] = 34816 (ends 69632)
#define SM_SSP 69632      // 256 f32
#define SM_B2S 70656      // 128 f32
#define SM_B3S 71168      // 64 f32
#define SM_W4S 71424      // 64 f32
#define SM_RED 71680      // 2*128 f32
#define SMEM_TOTAL 72704

// ---------------------------------------------------------------------------
// Precompute Qp/Sp. R4 fix: 160 CTAs (whole chip) + unroll-8 k loop so the
// W1 loads batch (MLP=8) instead of the serial MLP=1 that cost 72us.
// ---------------------------------------------------------------------------
__global__ void precompute_kernel(const float* __restrict__ qf,
                                  const float* __restrict__ sf,
                                  const float* __restrict__ W1,
                                  const float* __restrict__ b1)
{
    const int blk  = blockIdx.x;          // 0..127 -> Q, 128..159 -> S
    const bool isQ = (blk < 128);
    const int row0 = isQ ? blk * 8 : (blk - 128) * 8;
    const float* feat = isQ ? qf : sf;
    const int woff = isQ ? 0 : E;

    __shared__ float sF[8][E];
    const int tid = threadIdx.x;          // 256
    #pragma unroll
    for (int r = 0; r < 8; r++) sF[r][tid] = feat[(row0 + r) * E + tid];
    __syncthreads();

    const int j = tid;
    float acc[8];
    #pragma unroll
    for (int r = 0; r < 8; r++) acc[r] = 0.0f;

    #pragma unroll 8
    for (int k = 0; k < E; k++) {
        const float w = W1[(woff + k) * H1 + j];
        #pragma unroll
        for (int r = 0; r < 8; r++) acc[r] += sF[r][k] * w;
    }

    if (isQ) {
        #pragma unroll
        for (int r = 0; r < 8; r++) g_QpT[j * NQ + row0 + r] = acc[r];
    } else {
        const float bb = b1[j];
        #pragma unroll
        for (int r = 0; r < 8; r++) g_Sp[(row0 + r) * H1 + j] = acc[r] + bb;
    }
}

// Pre-split weights into fp16 hi/lo, padded mma-friendly layouts (bounded!)
__global__ void prep_weights_kernel(const float* __restrict__ W2,
                                    const float* __restrict__ W3)
{
    const int t = blockIdx.x * blockDim.x + threadIdx.x;   // 160*256 = 40960
    if (t < 8 * 5120) {
        const int c = t / 5120, r = t % 5120;
        const int n = r / 40, kk = r % 40;
        const float w = (kk < 32) ? W2[(c * 32 + kk) * H2 + n] : 0.0f;
        __half hi, lo; split_f16(w, hi, lo);
        g_W2TB_hi[c][r] = hi;
        g_W2TB_lo[c][r] = lo;
    }
    if (t < 8704) {
        const int n = t / 136, k = t % 136;
        const float w = (k < 128) ? W3[k * H3 + n] : 0.0f;
        __half hi, lo; split_f16(w, hi, lo);
        g_W3TB_hi[t] = hi;
        g_W3TB_lo[t] = lo;
    }
}

// ---------------------------------------------------------------------------
// Fused MLP: one CTA = 128 q-pairs x 1 support; layers 2..4 via mma.sync f16.
// B-corrected 2-term split: D = A_hi*(B_hi + B_lo); error = lo(A)*B ~ 2^-11.
// ---------------------------------------------------------------------------
__global__ void __launch_bounds__(256, 2)
relation_mma_kernel(const float* __restrict__ b2,
                    const float* __restrict__ b3,
                    const float* __restrict__ W4,
                    const float* __restrict__ b4,
                    float* __restrict__ out)
{
    extern __shared__ char smem[];
    const uint32_t sb = smem_to_u32(smem);
    const int tid  = threadIdx.x;
    const int lane = tid & 31;
    const int wid  = tid >> 5;
    const int wm   = wid & 3;          // 4 warps along M
    const int wn   = wid >> 2;         // 2 warps along N
    const int s_idx = blockIdx.x;
    const int q0    = blockIdx.y * TM;

    float* sSp = (float*)(smem + SM_SSP);
    float* b2s = (float*)(smem + SM_B2S);
    float* b3s = (float*)(smem + SM_B3S);
    float* W4s = (float*)(smem + SM_W4S);
    float* red = (float*)(smem + SM_RED);

    sSp[tid] = g_Sp[s_idx * H1 + tid];
    if (tid < H2) b2s[tid] = b2[tid];
    if (tid < H3) { b3s[tid] = b3[tid]; W4s[tid] = W4[tid]; }
    __syncthreads();

    float acc[2][8][4];
    #pragma unroll
    for (int a = 0; a < 2; a++)
        #pragma unroll
        for (int b = 0; b < 8; b++)
            #pragma unroll
            for (int c = 0; c < 4; c++) acc[a][b][c] = 0.0f;

    const int kk = tid >> 3;           // 0..31 (build: k row within chunk)
    const int qo = (tid & 7) * 16;     // 0..112 (build: q offset)

    // =================== layer2 mainloop: 8 chunks of k=32 ==================
    for (int c = 0; c < 8; ++c) {
        if (c) __syncthreads();

        // stage W2^T chunk (pre-split fp16): 640 float4 per table
        {
            const float4* gh = reinterpret_cast<const float4*>(g_W2TB_hi[c]);
            const float4* gl = reinterpret_cast<const float4*>(g_W2TB_lo[c]);
            float4* dh = reinterpret_cast<float4*>(smem + SM_B2H);
            float4* dl = reinterpret_cast<float4*>(smem + SM_B2L);
            #pragma unroll
            for (int i = 0; i < 3; ++i) {
                const int t = tid + 256 * i;
                if (t < 640) { dh[t] = gh[t]; dl[t] = gl[t]; }
            }
        }
        // build h1 chunk: relu(QpT + Sp) -> fp16 -> AT[k][m]
        {
            const float sp = sSp[c * 32 + kk];
            const float4* qp = reinterpret_cast<const float4*>(
                &g_QpT[(c * 32 + kk) * NQ + q0 + qo]);
            uint32_t* at = reinterpret_cast<uint32_t*>(smem + SM_AT);
            const int wbase = kk * 68 + (qo >> 1);
            #pragma unroll
            for (int v = 0; v < 4; ++v) {
                const float4 q4 = qp[v];
                const float x0 = frelu(q4.x + sp), x1 = frelu(q4.y + sp);
                const float x2 = frelu(q4.z + sp), x3 = frelu(q4.w + sp);
                at[wbase + 2*v    ] = pack2h(__float2half_rn(x0), __float2half_rn(x1));
                at[wbase + 2*v + 1] = pack2h(__float2half_rn(x2), __float2half_rn(x3));
            }
        }
        __syncthreads();

        // mma phase (2-term: A * B_hi + A * B_lo)
        #pragma unroll
        for (int ks = 0; ks < 2; ++ks) {
            uint32_t afr[2][4];
            const int arow = ks * 16 + (lane & 7) + 8 * (lane >> 4);
            #pragma unroll
            for (int tm = 0; tm < 2; ++tm) {
                const int acol = wm * 32 + tm * 16 + 8 * ((lane >> 3) & 1);
                ldsm4t(afr[tm], sb + SM_AT + arow * 272 + acol * 2);
            }
            #pragma unroll
            for (int tp = 0; tp < 4; ++tp) {
                uint32_t bh[4], bl[4];
                const int nrow = wn * 64 + tp * 16 + (lane & 7) + 8 * (lane >> 4);
                const int kcol = ks * 16 + 8 * ((lane >> 3) & 1);
                const uint32_t baddr = sb + SM_B2H + nrow * 80 + kcol * 2;
                ldsm4(bh, baddr);
                ldsm4(bl, baddr + (SM_B2L - SM_B2H));
                #pragma unroll
                for (int tm = 0; tm < 2; ++tm) {
                    mma_f16(acc[tm][2*tp    ], afr[tm], &bh[0]);
                    mma_f16(acc[tm][2*tp    ], afr[tm], &bl[0]);
                    mma_f16(acc[tm][2*tp + 1], afr[tm], &bh[2]);
                    mma_f16(acc[tm][2*tp + 1], afr[tm], &bl[2]);
                }
            }
        }
    }
    __syncthreads();   // staging free; h2/W3 regions safe to write

    // stage whole W3^T hi/lo: 1088 float4 each
    {
        const float4* gh = reinterpret_cast<const float4*>(g_W3TB_hi);
        const float4* gl = reinterpret_cast<const float4*>(g_W3TB_lo);
        float4* dh = reinterpret_cast<float4*>(smem + SM_W3H);
        float4* dl = reinterpret_cast<float4*>(smem + SM_W3L);
        #pragma unroll
        for (int i = 0; i < 5; ++i) {
            const int t = tid + 256 * i;
            if (t < 1088) { dh[t] = gh[t]; dl[t] = gl[t]; }
        }
    }
    // layer2 epilogue: bias+relu -> fp16 -> h2[m][k] (packed u32 stores)
    {
        uint32_t* hh = reinterpret_cast<uint32_t*>(smem + SM_H2);
        #pragma unroll
        for (int tm = 0; tm < 2; ++tm) {
            #pragma unroll
            for (int tn = 0; tn < 8; ++tn) {
                const int n = wn * 64 + tn * 8 + (lane & 3) * 2;
                const int m = wm * 32 + tm * 16 + (lane >> 2);
                const float bn0 = b2s[n], bn1 = b2s[n + 1];
                #pragma unroll
                for (int rr = 0; rr < 2; ++rr) {
                    const float x0 = frelu(acc[tm][tn][2*rr    ] + bn0);
                    const float x1 = frelu(acc[tm][tn][2*rr + 1] + bn1);
                    hh[(m + 8*rr) * 68 + (n >> 1)] =
                        pack2h(__float2half_rn(x0), __float2half_rn(x1));
                }
            }
        }
    }
    __syncthreads();

    // =================== layer3: h2[128x128] @ W3[128x64] ===================
    float acc3[2][4][4];
    #pragma unroll
    for (int a = 0; a < 2; a++)
        #pragma unroll
        for (int b = 0; b < 4; b++)
            #pragma unroll
            for (int c = 0; c < 4; c++) acc3[a][b][c] = 0.0f;

    #pragma unroll
    for (int ks = 0; ks < 8; ++ks) {
        uint32_t afr[2][4];
        #pragma unroll
        for (int tm = 0; tm < 2; ++tm) {
            const int mrow = wm * 32 + tm * 16 + (lane & 7) + 8 * ((lane >> 3) & 1);
            const int kcol = ks * 16 + 8 * (lane >> 4);
            ldsm4(afr[tm], sb + SM_H2 + mrow * 272 + kcol * 2);
        }
        #pragma unroll
        for (int tp = 0; tp < 2; ++tp) {
            uint32_t bh[4], bl[4];
            const int nrow = wn * 32 + tp * 16 + (lane & 7) + 8 * (lane >> 4);
            const int kcol = ks * 16 + 8 * ((lane >> 3) & 1);
            const uint32_t baddr = sb + SM_W3H + nrow * 272 + kcol * 2;
            ldsm4(bh, baddr);
            ldsm4(bl, baddr + (SM_W3L - SM_W3H));
            #pragma unroll
            for (int tm = 0; tm < 2; ++tm) {
                mma_f16(acc3[tm][2*tp    ], afr[tm], &bh[0]);
                mma_f16(acc3[tm][2*tp    ], afr[tm], &bl[0]);
                mma_f16(acc3[tm][2*tp + 1], afr[tm], &bh[2]);
                mma_f16(acc3[tm][2*tp + 1], afr[tm], &bl[2]);
            }
        }
    }

    // ============== layer3 epilogue + layer4 (registers + shfl) =============
    float part[4] = {0.0f, 0.0f, 0.0f, 0.0f};   // rows: tm*16 + rr*8 + (lane>>2)
    #pragma unroll
    for (int tn = 0; tn < 4; ++tn) {
        const int n = wn * 32 + tn * 8 + (lane & 3) * 2;
        const float bn0 = b3s[n], bn1 = b3s[n + 1];
        const float w0 = W4s[n],  w1 = W4s[n + 1];
        #pragma unroll
        for (int tm = 0; tm < 2; ++tm) {
            #pragma unroll
            for (int rr = 0; rr < 2; ++rr) {
                part[tm*2 + rr] += frelu(acc3[tm][tn][2*rr    ] + bn0) * w0
                                 + frelu(acc3[tm][tn][2*rr + 1] + bn1) * w1;
            }
        }
    }
    #pragma unroll
    for (int i = 0; i < 4; ++i) {
        part[i] += __shfl_xor_sync(0xffffffffu, part[i], 1);
        part[i] += __shfl_xor_sync(0xffffffffu, part[i], 2);
    }
    if ((lane & 3) == 0) {
        #pragma unroll
        for (int tm = 0; tm < 2; ++tm)
            #pragma unroll
            for (int rr = 0; rr < 2; ++rr) {
                const int m = wm * 32 + tm * 16 + rr * 8 + (lane >> 2);
                red[wn * 128 + m] = part[tm*2 + rr];
            }
    }
    __syncthreads();
    if (tid < 128) {
        const float v = red[tid] + red[128 + tid] + b4[0];
        out[(q0 + tid) * NS + s_idx] = 1.0f / (1.0f + expf(-v));
    }
}

// ---------------------------------------------------------------------------
extern "C" void kernel_launch(void* const* d_in, const int* in_sizes, int n_in,
                              void* d_out, int out_size)
{
    const float* qf = (const float*)d_in[0];
    const float* sf = (const float*)d_in[1];
    // d_in[2] = support_y (unused)
    const float* W1 = (const float*)d_in[3];
    const float* b1 = (const float*)d_in[4];
    const float* W2 = (const float*)d_in[5];
    const float* b2 = (const float*)d_in[6];
    const float* W3 = (const float*)d_in[7];
    const float* b3 = (const float*)d_in[8];
    const float* W4 = (const float*)d_in[9];
    const float* b4 = (const float*)d_in[10];
    float* out = (float*)d_out;

    cudaFuncSetAttribute(relation_mma_kernel,
                         cudaFuncAttributeMaxDynamicSharedMemorySize, SMEM_TOTAL);

    precompute_kernel<<<160, 256>>>(qf, sf, W1, b1);
    prep_weights_kernel<<<160, 256>>>(W2, W3);
    relation_mma_kernel<<<dim3(NS, NQ / TM), 256, SMEM_TOTAL>>>(b2, b3, W4, b4, out);
}

// round 6
// speedup vs baseline: 3.7998x; 1.2048x over previous
#include <cuda_runtime.h>
#include <cuda_fp16.h>
#include <math.h>
#include <stdint.h>

#define NQ 1024
#define NS 256
#define E  256
#define H1 256
#define H2 128
#define H3 64
#define TM 128          // query rows per CTA

// ---------------- warp-MMA helpers (plain sm_80+ PTX) -----------------------
__device__ __forceinline__ uint32_t smem_to_u32(const void* p) {
    uint32_t a;
    asm("{ .reg .u64 t; cvta.to.shared.u64 t, %1; cvt.u32.u64 %0, t; }" : "=r"(a) : "l"(p));
    return a;
}
__device__ __forceinline__ void ldsm4(uint32_t* r, uint32_t addr) {
    asm volatile("ldmatrix.sync.aligned.m8n8.x4.shared.b16 {%0,%1,%2,%3}, [%4];"
                 : "=r"(r[0]), "=r"(r[1]), "=r"(r[2]), "=r"(r[3]) : "r"(addr));
}
__device__ __forceinline__ void ldsm4t(uint32_t* r, uint32_t addr) {
    asm volatile("ldmatrix.sync.aligned.m8n8.x4.trans.shared.b16 {%0,%1,%2,%3}, [%4];"
                 : "=r"(r[0]), "=r"(r[1]), "=r"(r[2]), "=r"(r[3]) : "r"(addr));
}
__device__ __forceinline__ void mma_f16(float* d, const uint32_t* a, const uint32_t* b) {
    asm volatile("mma.sync.aligned.m16n8k16.row.col.f32.f16.f16.f32 "
                 "{%0,%1,%2,%3}, {%4,%5,%6,%7}, {%8,%9}, {%0,%1,%2,%3};"
                 : "+f"(d[0]), "+f"(d[1]), "+f"(d[2]), "+f"(d[3])
                 : "r"(a[0]), "r"(a[1]), "r"(a[2]), "r"(a[3]), "r"(b[0]), "r"(b[1]));
}
__device__ __forceinline__ void cp_async16(uint32_t dst_smem, const void* src) {
    asm volatile("cp.async.cg.shared.global [%0], [%1], 16;"
                 :: "r"(dst_smem), "l"(src));
}
#define CP_ASYNC_COMMIT() asm volatile("cp.async.commit_group;" ::: "memory")
#define CP_ASYNC_WAIT0()  asm volatile("cp.async.wait_group 0;" ::: "memory")

__device__ __forceinline__ void split_f16(float x, __half& hi, __half& lo) {
    hi = __float2half_rn(x);
    lo = __float2half_rn(x - __half2float(hi));
}
__device__ __forceinline__ uint32_t pack2h(__half a, __half b) {
    __half2 t; t.x = a; t.y = b;
    return *reinterpret_cast<uint32_t*>(&t);
}
__device__ __forceinline__ float frelu(float x) { return fmaxf(x, 0.0f); }

// ---------------- global scratch (static) -----------------------------------
__device__ float g_QpT[H1 * NQ];              // [k][q]
__device__ float g_Sp [NS * H1];              // [s][k] (+b1)
__device__ __half g_W2TB_hi[8][5120];         // [chunk][n*40 + kk], kk<32 data
__device__ __half g_W2TB_lo[8][5120];
__device__ __half g_W3TB_hi[8704];            // [n*136 + k], k<128 data
__device__ __half g_W3TB_lo[8704];

// ---------------- smem layout (bytes) ---------------------------------------
// phase A (double buffered):
#define SM_AT0  0         // h1^T fp16 [32k][136m] = 8704 per stage
#define SM_B2H0 17408     // W2^T hi [128n][40k] = 10240 ; lo at +10240
#define B2_STRIDE 20480   // per-stage (hi+lo)
// phase B (aliases phase A):
#define SM_W3H 0          // W3^T hi [64n][136k] = 17408
#define SM_W3L 17408      // lo (ends 34816)
#define SM_H2  34816      // h2 fp16 [128m][136k] = 34816 (ends 69632)
#define SM_SSP 69632      // 256 f32
#define SM_B2S 70656      // 128 f32
#define SM_B3S 71168      // 64 f32
#define SM_W4S 71424      // 64 f32
#define SM_RED 71680      // 2*128 f32
#define SMEM_TOTAL 72704

// ---------------------------------------------------------------------------
// Precompute Qp/Sp. R5 fix: 1024 threads/CTA with 4-way k-split (kq = tid>>8)
// -> 32 warps/CTA to hide L2 latency; smem reduction combines partials.
// ---------------------------------------------------------------------------
__global__ void __launch_bounds__(1024)
precompute_kernel(const float* __restrict__ qf,
                  const float* __restrict__ sf,
                  const float* __restrict__ W1,
                  const float* __restrict__ b1)
{
    const int blk  = blockIdx.x;          // 0..127 -> Q, 128..159 -> S
    const bool isQ = (blk < 128);
    const int row0 = isQ ? blk * 8 : (blk - 128) * 8;
    const float* feat = isQ ? qf : sf;
    const int woff = isQ ? 0 : E;

    __shared__ float sF[8][E];
    __shared__ float part[3][8][256];
    const int tid = threadIdx.x;          // 1024
    const int j  = tid & 255;
    const int kq = tid >> 8;              // 0..3 (k quarter)

    {
        const int t0 = tid;
        sF[t0 >> 8][t0 & 255] = feat[(row0 + (t0 >> 8)) * E + (t0 & 255)];
        const int t1 = tid + 1024;
        sF[t1 >> 8][t1 & 255] = feat[(row0 + (t1 >> 8)) * E + (t1 & 255)];
    }
    __syncthreads();

    float acc[8];
    #pragma unroll
    for (int r = 0; r < 8; r++) acc[r] = 0.0f;

    const int k0 = kq * 64;
    #pragma unroll 8
    for (int k = k0; k < k0 + 64; ++k) {
        const float w = W1[(woff + k) * H1 + j];
        #pragma unroll
        for (int r = 0; r < 8; r++) acc[r] += sF[r][k] * w;
    }

    if (kq) {
        #pragma unroll
        for (int r = 0; r < 8; r++) part[kq - 1][r][j] = acc[r];
    }
    __syncthreads();
    if (kq == 0) {
        #pragma unroll
        for (int r = 0; r < 8; r++)
            acc[r] += part[0][r][j] + part[1][r][j] + part[2][r][j];
        if (isQ) {
            #pragma unroll
            for (int r = 0; r < 8; r++) g_QpT[j * NQ + row0 + r] = acc[r];
        } else {
            const float bb = b1[j];
            #pragma unroll
            for (int r = 0; r < 8; r++) g_Sp[(row0 + r) * H1 + j] = acc[r] + bb;
        }
    }
}

// Pre-split weights into fp16 hi/lo, padded mma-friendly layouts (bounded)
__global__ void prep_weights_kernel(const float* __restrict__ W2,
                                    const float* __restrict__ W3)
{
    const int t = blockIdx.x * blockDim.x + threadIdx.x;   // 160*256 = 40960
    if (t < 8 * 5120) {
        const int c = t / 5120, r = t % 5120;
        const int n = r / 40, kk = r % 40;
        const float w = (kk < 32) ? W2[(c * 32 + kk) * H2 + n] : 0.0f;
        __half hi, lo; split_f16(w, hi, lo);
        g_W2TB_hi[c][r] = hi;
        g_W2TB_lo[c][r] = lo;
    }
    if (t < 8704) {
        const int n = t / 136, k = t % 136;
        const float w = (k < 128) ? W3[k * H3 + n] : 0.0f;
        __half hi, lo; split_f16(w, hi, lo);
        g_W3TB_hi[t] = hi;
        g_W3TB_lo[t] = lo;
    }
}

// ---------------------------------------------------------------------------
// Fused MLP: one CTA = 128 q-pairs x 1 support; layers 2..4 via mma.sync f16.
// R5: software-pipelined mainloop (cp.async W2 staging + reg-prefetched QpT,
// double-buffered smem, one sync per chunk).
// ---------------------------------------------------------------------------
__global__ void __launch_bounds__(256, 2)
relation_mma_kernel(const float* __restrict__ b2,
                    const float* __restrict__ b3,
                    const float* __restrict__ W4,
                    const float* __restrict__ b4,
                    float* __restrict__ out)
{
    extern __shared__ char smem[];
    const uint32_t sb = smem_to_u32(smem);
    const int tid  = threadIdx.x;
    const int lane = tid & 31;
    const int wid  = tid >> 5;
    const int wm   = wid & 3;          // 4 warps along M
    const int wn   = wid >> 2;         // 2 warps along N
    const int s_idx = blockIdx.x;
    const int q0    = blockIdx.y * TM;

    float* sSp = (float*)(smem + SM_SSP);
    float* b2s = (float*)(smem + SM_B2S);
    float* b3s = (float*)(smem + SM_B3S);
    float* W4s = (float*)(smem + SM_W4S);
    float* red = (float*)(smem + SM_RED);

    sSp[tid] = g_Sp[s_idx * H1 + tid];
    if (tid < H2) b2s[tid] = b2[tid];
    if (tid < H3) { b3s[tid] = b3[tid]; W4s[tid] = W4[tid]; }

    const int kk = tid >> 3;           // 0..31 (build: k row within chunk)
    const int qo = (tid & 7) * 16;     // 0..112 (build: q offset)

    // ---- prologue: cp.async W2 chunk0 -> buf0; prefetch QpT chunk0 regs ----
    {
        const char* srcH = (const char*)g_W2TB_hi[0];
        const char* srcL = (const char*)g_W2TB_lo[0];
        const uint32_t dstH = sb + SM_B2H0;
        #pragma unroll
        for (int i = 0; i < 3; ++i) {
            const int t = tid + 256 * i;
            if (t < 640) {
                cp_async16(dstH + t * 16, srcH + t * 16);
                cp_async16(dstH + 10240 + t * 16, srcL + t * 16);
            }
        }
        CP_ASYNC_COMMIT();
    }
    float4 qv0, qv1, qv2, qv3;
    {
        const float4* qp = reinterpret_cast<const float4*>(&g_QpT[kk * NQ + q0 + qo]);
        qv0 = qp[0]; qv1 = qp[1]; qv2 = qp[2]; qv3 = qp[3];
    }
    __syncthreads();   // sSp/b2s visible

    float acc[2][8][4];
    #pragma unroll
    for (int a = 0; a < 2; a++)
        #pragma unroll
        for (int b = 0; b < 8; b++)
            #pragma unroll
            for (int c = 0; c < 4; c++) acc[a][b][c] = 0.0f;

    // =================== layer2 pipelined mainloop: 8 chunks of k=32 ========
    for (int c = 0; c < 8; ++c) {
        const int st = c & 1;
        // build h1 chunk from prefetched regs -> AT[st]
        {
            const float sp = sSp[c * 32 + kk];
            uint32_t* at = reinterpret_cast<uint32_t*>(smem + SM_AT0 + st * 8704);
            const int wbase = kk * 68 + (qo >> 1);
            const float4 q4[4] = {qv0, qv1, qv2, qv3};
            #pragma unroll
            for (int v = 0; v < 4; ++v) {
                const float x0 = frelu(q4[v].x + sp), x1 = frelu(q4[v].y + sp);
                const float x2 = frelu(q4[v].z + sp), x3 = frelu(q4[v].w + sp);
                at[wbase + 2*v    ] = pack2h(__float2half_rn(x0), __float2half_rn(x1));
                at[wbase + 2*v + 1] = pack2h(__float2half_rn(x2), __float2half_rn(x3));
            }
        }
        CP_ASYNC_WAIT0();      // W2 chunk c arrived
        __syncthreads();       // AT[st] + W2 buf[st] visible; prev reads done

        if (c < 7) {
            // issue W2 chunk c+1 into the other buffer (overlaps with mma)
            const char* srcH = (const char*)g_W2TB_hi[c + 1];
            const char* srcL = (const char*)g_W2TB_lo[c + 1];
            const uint32_t dstH = sb + SM_B2H0 + (st ^ 1) * B2_STRIDE;
            #pragma unroll
            for (int i = 0; i < 3; ++i) {
                const int t = tid + 256 * i;
                if (t < 640) {
                    cp_async16(dstH + t * 16, srcH + t * 16);
                    cp_async16(dstH + 10240 + t * 16, srcL + t * 16);
                }
            }
            CP_ASYNC_COMMIT();
            // prefetch QpT chunk c+1 (latency hidden under mma below)
            const float4* qp = reinterpret_cast<const float4*>(
                &g_QpT[((c + 1) * 32 + kk) * NQ + q0 + qo]);
            qv0 = qp[0]; qv1 = qp[1]; qv2 = qp[2]; qv3 = qp[3];
        }

        // mma phase (2-term: A * B_hi + A * B_lo)
        const uint32_t atb = sb + SM_AT0 + st * 8704;
        const uint32_t b2b = sb + SM_B2H0 + st * B2_STRIDE;
        #pragma unroll
        for (int ks = 0; ks < 2; ++ks) {
            uint32_t afr[2][4];
            const int arow = ks * 16 + (lane & 7) + 8 * (lane >> 4);
            #pragma unroll
            for (int tm = 0; tm < 2; ++tm) {
                const int acol = wm * 32 + tm * 16 + 8 * ((lane >> 3) & 1);
                ldsm4t(afr[tm], atb + arow * 272 + acol * 2);
            }
            #pragma unroll
            for (int tp = 0; tp < 4; ++tp) {
                uint32_t bh[4], bl[4];
                const int nrow = wn * 64 + tp * 16 + (lane & 7) + 8 * (lane >> 4);
                const int kcol = ks * 16 + 8 * ((lane >> 3) & 1);
                const uint32_t baddr = b2b + nrow * 80 + kcol * 2;
                ldsm4(bh, baddr);
                ldsm4(bl, baddr + 10240);
                #pragma unroll
                for (int tm = 0; tm < 2; ++tm) {
                    mma_f16(acc[tm][2*tp    ], afr[tm], &bh[0]);
                    mma_f16(acc[tm][2*tp    ], afr[tm], &bl[0]);
                    mma_f16(acc[tm][2*tp + 1], afr[tm], &bh[2]);
                    mma_f16(acc[tm][2*tp + 1], afr[tm], &bl[2]);
                }
            }
        }
    }
    __syncthreads();   // all mainloop smem reads done; phase-A buffers dead

    // stage whole W3^T hi/lo via cp.async (overlaps with epilogue below)
    {
        const char* srcH = (const char*)g_W3TB_hi;
        const char* srcL = (const char*)g_W3TB_lo;
        #pragma unroll
        for (int i = 0; i < 5; ++i) {
            const int t = tid + 256 * i;
            if (t < 1088) {
                cp_async16(sb + SM_W3H + t * 16, srcH + t * 16);
                cp_async16(sb + SM_W3L + t * 16, srcL + t * 16);
            }
        }
        CP_ASYNC_COMMIT();
    }
    // layer2 epilogue: bias+relu -> fp16 -> h2[m][k] (packed u32 stores)
    {
        uint32_t* hh = reinterpret_cast<uint32_t*>(smem + SM_H2);
        #pragma unroll
        for (int tm = 0; tm < 2; ++tm) {
            #pragma unroll
            for (int tn = 0; tn < 8; ++tn) {
                const int n = wn * 64 + tn * 8 + (lane & 3) * 2;
                const int m = wm * 32 + tm * 16 + (lane >> 2);
                const float bn0 = b2s[n], bn1 = b2s[n + 1];
                #pragma unroll
                for (int rr = 0; rr < 2; ++rr) {
                    const float x0 = frelu(acc[tm][tn][2*rr    ] + bn0);
                    const float x1 = frelu(acc[tm][tn][2*rr + 1] + bn1);
                    hh[(m + 8*rr) * 68 + (n >> 1)] =
                        pack2h(__float2half_rn(x0), __float2half_rn(x1));
                }
            }
        }
    }
    CP_ASYNC_WAIT0();
    __syncthreads();

    // =================== layer3: h2[128x128] @ W3[128x64] ===================
    float acc3[2][4][4];
    #pragma unroll
    for (int a = 0; a < 2; a++)
        #pragma unroll
        for (int b = 0; b < 4; b++)
            #pragma unroll
            for (int c = 0; c < 4; c++) acc3[a][b][c] = 0.0f;

    #pragma unroll
    for (int ks = 0; ks < 8; ++ks) {
        uint32_t afr[2][4];
        #pragma unroll
        for (int tm = 0; tm < 2; ++tm) {
            const int mrow = wm * 32 + tm * 16 + (lane & 7) + 8 * ((lane >> 3) & 1);
            const int kcol = ks * 16 + 8 * (lane >> 4);
            ldsm4(afr[tm], sb + SM_H2 + mrow * 272 + kcol * 2);
        }
        #pragma unroll
        for (int tp = 0; tp < 2; ++tp) {
            uint32_t bh[4], bl[4];
            const int nrow = wn * 32 + tp * 16 + (lane & 7) + 8 * (lane >> 4);
            const int kcol = ks * 16 + 8 * ((lane >> 3) & 1);
            const uint32_t baddr = sb + SM_W3H + nrow * 272 + kcol * 2;
            ldsm4(bh, baddr);
            ldsm4(bl, baddr + (SM_W3L - SM_W3H));
            #pragma unroll
            for (int tm = 0; tm < 2; ++tm) {
                mma_f16(acc3[tm][2*tp    ], afr[tm], &bh[0]);
                mma_f16(acc3[tm][2*tp    ], afr[tm], &bl[0]);
                mma_f16(acc3[tm][2*tp + 1], afr[tm], &bh[2]);
                mma_f16(acc3[tm][2*tp + 1], afr[tm], &bl[2]);
            }
        }
    }

    // ============== layer3 epilogue + layer4 (registers + shfl) =============
    float part[4] = {0.0f, 0.0f, 0.0f, 0.0f};   // rows: tm*16 + rr*8 + (lane>>2)
    #pragma unroll
    for (int tn = 0; tn < 4; ++tn) {
        const int n = wn * 32 + tn * 8 + (lane & 3) * 2;
        const float bn0 = b3s[n], bn1 = b3s[n + 1];
        const float w0 = W4s[n],  w1 = W4s[n + 1];
        #pragma unroll
        for (int tm = 0; tm < 2; ++tm) {
            #pragma unroll
            for (int rr = 0; rr < 2; ++rr) {
                part[tm*2 + rr] += frelu(acc3[tm][tn][2*rr    ] + bn0) * w0
                                 + frelu(acc3[tm][tn][2*rr + 1] + bn1) * w1;
            }
        }
    }
    #pragma unroll
    for (int i = 0; i < 4; ++i) {
        part[i] += __shfl_xor_sync(0xffffffffu, part[i], 1);
        part[i] += __shfl_xor_sync(0xffffffffu, part[i], 2);
    }
    if ((lane & 3) == 0) {
        #pragma unroll
        for (int tm = 0; tm < 2; ++tm)
            #pragma unroll
            for (int rr = 0; rr < 2; ++rr) {
                const int m = wm * 32 + tm * 16 + rr * 8 + (lane >> 2);
                red[wn * 128 + m] = part[tm*2 + rr];
            }
    }
    __syncthreads();
    if (tid < 128) {
        const float v = red[tid] + red[128 + tid] + b4[0];
        out[(q0 + tid) * NS + s_idx] = 1.0f / (1.0f + expf(-v));
    }
}

// ---------------------------------------------------------------------------
extern "C" void kernel_launch(void* const* d_in, const int* in_sizes, int n_in,
                              void* d_out, int out_size)
{
    const float* qf = (const float*)d_in[0];
    const float* sf = (const float*)d_in[1];
    // d_in[2] = support_y (unused)
    const float* W1 = (const float*)d_in[3];
    const float* b1 = (const float*)d_in[4];
    const float* W2 = (const float*)d_in[5];
    const float* b2 = (const float*)d_in[6];
    const float* W3 = (const float*)d_in[7];
    const float* b3 = (const float*)d_in[8];
    const float* W4 = (const float*)d_in[9];
    const float* b4 = (const float*)d_in[10];
    float* out = (float*)d_out;

    cudaFuncSetAttribute(relation_mma_kernel,
                         cudaFuncAttributeMaxDynamicSharedMemorySize, SMEM_TOTAL);

    precompute_kernel<<<160, 1024>>>(qf, sf, W1, b1);
    prep_weights_kernel<<<160, 256>>>(W2, W3);
    relation_mma_kernel<<<dim3(NS, NQ / TM), 256, SMEM_TOTAL>>>(b2, b3, W4, b4, out);
}

// round 7
// speedup vs baseline: 4.7497x; 1.2500x over previous
#include <cuda_runtime.h>
#include <cuda_fp16.h>
#include <math.h>
#include <stdint.h>

#define NQ 1024
#define NS 256
#define E  256
#define H1 256
#define H2 128
#define H3 64
#define TM 128          // query rows per CTA

// ---------------- warp-MMA helpers (plain sm_80+ PTX) -----------------------
__device__ __forceinline__ uint32_t smem_to_u32(const void* p) {
    uint32_t a;
    asm("{ .reg .u64 t; cvta.to.shared.u64 t, %1; cvt.u32.u64 %0, t; }" : "=r"(a) : "l"(p));
    return a;
}
__device__ __forceinline__ void ldsm4(uint32_t* r, uint32_t addr) {
    asm volatile("ldmatrix.sync.aligned.m8n8.x4.shared.b16 {%0,%1,%2,%3}, [%4];"
                 : "=r"(r[0]), "=r"(r[1]), "=r"(r[2]), "=r"(r[3]) : "r"(addr));
}
__device__ __forceinline__ void ldsm4t(uint32_t* r, uint32_t addr) {
    asm volatile("ldmatrix.sync.aligned.m8n8.x4.trans.shared.b16 {%0,%1,%2,%3}, [%4];"
                 : "=r"(r[0]), "=r"(r[1]), "=r"(r[2]), "=r"(r[3]) : "r"(addr));
}
__device__ __forceinline__ void mma_f16(float* d, const uint32_t* a, const uint32_t* b) {
    asm volatile("mma.sync.aligned.m16n8k16.row.col.f32.f16.f16.f32 "
                 "{%0,%1,%2,%3}, {%4,%5,%6,%7}, {%8,%9}, {%0,%1,%2,%3};"
                 : "+f"(d[0]), "+f"(d[1]), "+f"(d[2]), "+f"(d[3])
                 : "r"(a[0]), "r"(a[1]), "r"(a[2]), "r"(a[3]), "r"(b[0]), "r"(b[1]));
}
__device__ __forceinline__ void cp_async16(uint32_t dst_smem, const void* src) {
    asm volatile("cp.async.cg.shared.global [%0], [%1], 16;"
                 :: "r"(dst_smem), "l"(src));
}
#define CP_ASYNC_COMMIT() asm volatile("cp.async.commit_group;" ::: "memory")
#define CP_ASYNC_WAIT0()  asm volatile("cp.async.wait_group 0;" ::: "memory")

__device__ __forceinline__ void split_f16(float x, __half& hi, __half& lo) {
    hi = __float2half_rn(x);
    lo = __float2half_rn(x - __half2float(hi));
}
__device__ __forceinline__ uint32_t pack2h(__half a, __half b) {
    __half2 t; t.x = a; t.y = b;
    return *reinterpret_cast<uint32_t*>(&t);
}
__device__ __forceinline__ float frelu(float x) { return fmaxf(x, 0.0f); }

// ---------------- global scratch (static) -----------------------------------
__device__ float g_QpT[H1 * NQ];              // [k][q]
__device__ float g_Sp [NS * H1];              // [s][k] (+b1)
__device__ __half g_W1TB_hi[163840];          // [(half*8+c)*256+n]*40+kk (kk<32)
__device__ __half g_W1TB_lo[163840];
__device__ __half g_W2TB[8][5120];            // [chunk][n*40+kk] fp16 (hi only)
__device__ __half g_W3TB[8704];               // [n*136+k] fp16 (hi only)

// ---------------- main-kernel smem layout (bytes) ----------------------------
// phase A (double buffered):
#define SM_AT0  0         // h1^T fp16 [32k][136m] = 8704 per stage (x2 = 17408)
#define SM_B2H0 17408     // W2^T hi [128n][40k] = 10240 per stage (x2 = 20480)
#define B2_STRIDE 10240
// phase B (aliases phase A):
#define SM_W3  0          // W3^T [64n][136k] = 17408
#define SM_H2  17408      // h2 fp16 [128m][136k] = 34816 (ends 52224)
#define SM_SSP 52224      // 256 f32
#define SM_B2S 53248      // 128 f32
#define SM_B3S 53760      // 64 f32
#define SM_W4S 54016      // 64 f32
#define SM_RED 54272      // 2*128 f32
#define SMEM_TOTAL 55296

// ---------------- precompute-kernel smem layout ------------------------------
#define PSM_A  0          // feat fp16 [128m][264k] = 67584
#define PSM_B  67584      // W1 stage: 2 x (hi 10240 + lo 10240) = 40960
#define PB_STRIDE 20480
#define PRE_SMEM_TOTAL 108544

// ---------------------------------------------------------------------------
// Weight prep: W1 -> fp16 hi/lo transposed+padded; W2/W3 -> fp16 (hi only)
// ---------------------------------------------------------------------------
__global__ void prep_weights_kernel(const float* __restrict__ W1,
                                    const float* __restrict__ W2,
                                    const float* __restrict__ W3)
{
    const int t = blockIdx.x * blockDim.x + threadIdx.x;   // 640*256 = 163840
    if (t < 163840) {
        const int kk = t % 40;
        const int n  = (t / 40) & 255;
        const int c  = (t / (40 * 256)) & 7;
        const int hf = t / (40 * 256 * 8);
        const float w = (kk < 32) ? W1[(hf * 256 + c * 32 + kk) * H1 + n] : 0.0f;
        __half hi, lo; split_f16(w, hi, lo);
        g_W1TB_hi[t] = hi;
        g_W1TB_lo[t] = lo;
    }
    if (t < 8 * 5120) {
        const int c = t / 5120, r = t % 5120;
        const int n = r / 40, kk = r % 40;
        const float w = (kk < 32) ? W2[(c * 32 + kk) * H2 + n] : 0.0f;
        g_W2TB[c][r] = __float2half_rn(w);
    }
    if (t < 8704) {
        const int n = t / 136, k = t % 136;
        const float w = (k < 128) ? W3[k * H3 + n] : 0.0f;
        g_W3TB[t] = __float2half_rn(w);
    }
}

// ---------------------------------------------------------------------------
// Precompute via mma: Out = feat @ W1half (+b1 for S). 20 CTAs:
//   mb 0..7 -> Q blocks (128 q rows), mb 8..9 -> S blocks; nb 0..1 (N=128).
// W1 staged hi+lo (2-term B split) so this step adds no fp16-weight error.
// ---------------------------------------------------------------------------
__global__ void __launch_bounds__(256)
precompute_mma_kernel(const float* __restrict__ qf,
                      const float* __restrict__ sf,
                      const float* __restrict__ b1)
{
    extern __shared__ char smem[];
    const uint32_t sb = smem_to_u32(smem);
    const int tid  = threadIdx.x;
    const int lane = tid & 31;
    const int wid  = tid >> 5;
    const int wm   = wid & 3;          // 4 warps along M
    const int wn   = wid >> 2;         // 2 warps along N
    const int mb   = blockIdx.x;       // 0..9
    const int nb   = blockIdx.y;       // 0..1
    const bool isQ = (mb < 8);
    const float* feat = isQ ? (qf + mb * 128 * E) : (sf + (mb - 8) * 128 * E);
    const int hf = isQ ? 0 : 1;

    // ---- stage A: feat[128][256] f32 -> fp16 smem [128][264] ----
    {
        const int row = tid >> 1, hv = tid & 1;
        const float4* src = reinterpret_cast<const float4*>(feat + row * E);
        uint32_t* dst = reinterpret_cast<uint32_t*>(smem + PSM_A);
        #pragma unroll 8
        for (int j = 0; j < 32; ++j) {
            const float4 v = src[hv * 32 + j];
            const int u = row * 132 + (hv * 32 + j) * 2;
            dst[u]     = pack2h(__float2half_rn(v.x), __float2half_rn(v.y));
            dst[u + 1] = pack2h(__float2half_rn(v.z), __float2half_rn(v.w));
        }
    }
    // ---- prologue: W1 chunk0 hi+lo via cp.async ----
    {
        const char* srcH = (const char*)&g_W1TB_hi[((hf * 8 + 0) * 256 + nb * 128) * 40];
        const char* srcL = (const char*)&g_W1TB_lo[((hf * 8 + 0) * 256 + nb * 128) * 40];
        const uint32_t dstH = sb + PSM_B;
        #pragma unroll
        for (int i = 0; i < 3; ++i) {
            const int t = tid + 256 * i;
            if (t < 640) {
                cp_async16(dstH + t * 16, srcH + t * 16);
                cp_async16(dstH + 10240 + t * 16, srcL + t * 16);
            }
        }
        CP_ASYNC_COMMIT();
    }
    __syncthreads();

    float acc[2][8][4];
    #pragma unroll
    for (int a = 0; a < 2; a++)
        #pragma unroll
        for (int b = 0; b < 8; b++)
            #pragma unroll
            for (int c = 0; c < 4; c++) acc[a][b][c] = 0.0f;

    for (int c = 0; c < 8; ++c) {
        const int st = c & 1;
        CP_ASYNC_WAIT0();
        __syncthreads();
        if (c < 7) {
            const int base = ((hf * 8 + c + 1) * 256 + nb * 128) * 40;
            const char* srcH = (const char*)&g_W1TB_hi[base];
            const char* srcL = (const char*)&g_W1TB_lo[base];
            const uint32_t dstH = sb + PSM_B + (st ^ 1) * PB_STRIDE;
            #pragma unroll
            for (int i = 0; i < 3; ++i) {
                const int t = tid + 256 * i;
                if (t < 640) {
                    cp_async16(dstH + t * 16, srcH + t * 16);
                    cp_async16(dstH + 10240 + t * 16, srcL + t * 16);
                }
            }
            CP_ASYNC_COMMIT();
        }
        const uint32_t bufH = sb + PSM_B + st * PB_STRIDE;
        #pragma unroll
        for (int ks = 0; ks < 2; ++ks) {
            uint32_t afr[2][4];
            #pragma unroll
            for (int tm = 0; tm < 2; ++tm) {
                const int mrow = wm * 32 + tm * 16 + (lane & 7) + 8 * ((lane >> 3) & 1);
                const int kcol = c * 32 + ks * 16 + 8 * (lane >> 4);
                ldsm4(afr[tm], sb + PSM_A + mrow * 528 + kcol * 2);
            }
            #pragma unroll
            for (int tp = 0; tp < 4; ++tp) {
                uint32_t bh[4], bl[4];
                const int nrow = wn * 64 + tp * 16 + (lane & 7) + 8 * (lane >> 4);
                const int kcol = ks * 16 + 8 * ((lane >> 3) & 1);
                const uint32_t baddr = bufH + nrow * 80 + kcol * 2;
                ldsm4(bh, baddr);
                ldsm4(bl, baddr + 10240);
                #pragma unroll
                for (int tm = 0; tm < 2; ++tm) {
                    mma_f16(acc[tm][2*tp    ], afr[tm], &bh[0]);
                    mma_f16(acc[tm][2*tp    ], afr[tm], &bl[0]);
                    mma_f16(acc[tm][2*tp + 1], afr[tm], &bh[2]);
                    mma_f16(acc[tm][2*tp + 1], afr[tm], &bl[2]);
                }
            }
        }
    }

    // ---- epilogue: scatter to g_QpT / g_Sp ----
    if (isQ) {
        const int q0 = mb * 128;
        #pragma unroll
        for (int tm = 0; tm < 2; ++tm)
            #pragma unroll
            for (int tn = 0; tn < 8; ++tn) {
                const int n = nb * 128 + wn * 64 + tn * 8 + (lane & 3) * 2;
                #pragma unroll
                for (int rr = 0; rr < 2; ++rr) {
                    const int m = wm * 32 + tm * 16 + rr * 8 + (lane >> 2);
                    g_QpT[n * NQ + q0 + m]       = acc[tm][tn][2*rr];
                    g_QpT[(n + 1) * NQ + q0 + m] = acc[tm][tn][2*rr + 1];
                }
            }
    } else {
        const int s0 = (mb - 8) * 128;
        #pragma unroll
        for (int tm = 0; tm < 2; ++tm)
            #pragma unroll
            for (int tn = 0; tn < 8; ++tn) {
                const int n = nb * 128 + wn * 64 + tn * 8 + (lane & 3) * 2;
                const float bb0 = b1[n], bb1 = b1[n + 1];
                #pragma unroll
                for (int rr = 0; rr < 2; ++rr) {
                    const int m = wm * 32 + tm * 16 + rr * 8 + (lane >> 2);
                    g_Sp[(s0 + m) * H1 + n]     = acc[tm][tn][2*rr]     + bb0;
                    g_Sp[(s0 + m) * H1 + n + 1] = acc[tm][tn][2*rr + 1] + bb1;
                }
            }
    }
}

// ---------------------------------------------------------------------------
// Fused MLP: one CTA = 128 q-pairs x 1 support; layers 2..4 via mma.sync f16.
// R6: B-side single fp16 (hi only) -> half the MMA count; pipelined mainloop.
// ---------------------------------------------------------------------------
__global__ void __launch_bounds__(256, 2)
relation_mma_kernel(const float* __restrict__ b2,
                    const float* __restrict__ b3,
                    const float* __restrict__ W4,
                    const float* __restrict__ b4,
                    float* __restrict__ out)
{
    extern __shared__ char smem[];
    const uint32_t sb = smem_to_u32(smem);
    const int tid  = threadIdx.x;
    const int lane = tid & 31;
    const int wid  = tid >> 5;
    const int wm   = wid & 3;          // 4 warps along M
    const int wn   = wid >> 2;         // 2 warps along N
    const int s_idx = blockIdx.x;
    const int q0    = blockIdx.y * TM;

    float* sSp = (float*)(smem + SM_SSP);
    float* b2s = (float*)(smem + SM_B2S);
    float* b3s = (float*)(smem + SM_B3S);
    float* W4s = (float*)(smem + SM_W4S);
    float* red = (float*)(smem + SM_RED);

    sSp[tid] = g_Sp[s_idx * H1 + tid];
    if (tid < H2) b2s[tid] = b2[tid];
    if (tid < H3) { b3s[tid] = b3[tid]; W4s[tid] = W4[tid]; }

    const int kk = tid >> 3;           // 0..31 (build: k row within chunk)
    const int qo = (tid & 7) * 16;     // 0..112 (build: q offset)

    // ---- prologue: cp.async W2 chunk0 -> buf0; prefetch QpT chunk0 regs ----
    {
        const char* srcH = (const char*)g_W2TB[0];
        const uint32_t dstH = sb + SM_B2H0;
        #pragma unroll
        for (int i = 0; i < 3; ++i) {
            const int t = tid + 256 * i;
            if (t < 640) cp_async16(dstH + t * 16, srcH + t * 16);
        }
        CP_ASYNC_COMMIT();
    }
    float4 qv0, qv1, qv2, qv3;
    {
        const float4* qp = reinterpret_cast<const float4*>(&g_QpT[kk * NQ + q0 + qo]);
        qv0 = qp[0]; qv1 = qp[1]; qv2 = qp[2]; qv3 = qp[3];
    }
    __syncthreads();   // sSp/b2s visible

    float acc[2][8][4];
    #pragma unroll
    for (int a = 0; a < 2; a++)
        #pragma unroll
        for (int b = 0; b < 8; b++)
            #pragma unroll
            for (int c = 0; c < 4; c++) acc[a][b][c] = 0.0f;

    // =================== layer2 pipelined mainloop: 8 chunks of k=32 ========
    for (int c = 0; c < 8; ++c) {
        const int st = c & 1;
        // build h1 chunk from prefetched regs -> AT[st]
        {
            const float sp = sSp[c * 32 + kk];
            uint32_t* at = reinterpret_cast<uint32_t*>(smem + SM_AT0 + st * 8704);
            const int wbase = kk * 68 + (qo >> 1);
            const float4 q4[4] = {qv0, qv1, qv2, qv3};
            #pragma unroll
            for (int v = 0; v < 4; ++v) {
                const float x0 = frelu(q4[v].x + sp), x1 = frelu(q4[v].y + sp);
                const float x2 = frelu(q4[v].z + sp), x3 = frelu(q4[v].w + sp);
                at[wbase + 2*v    ] = pack2h(__float2half_rn(x0), __float2half_rn(x1));
                at[wbase + 2*v + 1] = pack2h(__float2half_rn(x2), __float2half_rn(x3));
            }
        }
        CP_ASYNC_WAIT0();      // W2 chunk c arrived
        __syncthreads();       // AT[st] + W2 buf[st] visible; prev reads done

        if (c < 7) {
            const char* srcH = (const char*)g_W2TB[c + 1];
            const uint32_t dstH = sb + SM_B2H0 + (st ^ 1) * B2_STRIDE;
            #pragma unroll
            for (int i = 0; i < 3; ++i) {
                const int t = tid + 256 * i;
                if (t < 640) cp_async16(dstH + t * 16, srcH + t * 16);
            }
            CP_ASYNC_COMMIT();
            const float4* qp = reinterpret_cast<const float4*>(
                &g_QpT[((c + 1) * 32 + kk) * NQ + q0 + qo]);
            qv0 = qp[0]; qv1 = qp[1]; qv2 = qp[2]; qv3 = qp[3];
        }

        // mma phase (B hi only)
        const uint32_t atb = sb + SM_AT0 + st * 8704;
        const uint32_t b2b = sb + SM_B2H0 + st * B2_STRIDE;
        #pragma unroll
        for (int ks = 0; ks < 2; ++ks) {
            uint32_t afr[2][4];
            const int arow = ks * 16 + (lane & 7) + 8 * (lane >> 4);
            #pragma unroll
            for (int tm = 0; tm < 2; ++tm) {
                const int acol = wm * 32 + tm * 16 + 8 * ((lane >> 3) & 1);
                ldsm4t(afr[tm], atb + arow * 272 + acol * 2);
            }
            #pragma unroll
            for (int tp = 0; tp < 4; ++tp) {
                uint32_t bh[4];
                const int nrow = wn * 64 + tp * 16 + (lane & 7) + 8 * (lane >> 4);
                const int kcol = ks * 16 + 8 * ((lane >> 3) & 1);
                ldsm4(bh, b2b + nrow * 80 + kcol * 2);
                #pragma unroll
                for (int tm = 0; tm < 2; ++tm) {
                    mma_f16(acc[tm][2*tp    ], afr[tm], &bh[0]);
                    mma_f16(acc[tm][2*tp + 1], afr[tm], &bh[2]);
                }
            }
        }
    }
    __syncthreads();   // all mainloop smem reads done; phase-A buffers dead

    // stage whole W3^T via cp.async (overlaps with epilogue below)
    {
        const char* srcH = (const char*)g_W3TB;
        #pragma unroll
        for (int i = 0; i < 5; ++i) {
            const int t = tid + 256 * i;
            if (t < 1088) cp_async16(sb + SM_W3 + t * 16, srcH + t * 16);
        }
        CP_ASYNC_COMMIT();
    }
    // layer2 epilogue: bias+relu -> fp16 -> h2[m][k] (packed u32 stores)
    {
        uint32_t* hh = reinterpret_cast<uint32_t*>(smem + SM_H2);
        #pragma unroll
        for (int tm = 0; tm < 2; ++tm) {
            #pragma unroll
            for (int tn = 0; tn < 8; ++tn) {
                const int n = wn * 64 + tn * 8 + (lane & 3) * 2;
                const int m = wm * 32 + tm * 16 + (lane >> 2);
                const float bn0 = b2s[n], bn1 = b2s[n + 1];
                #pragma unroll
                for (int rr = 0; rr < 2; ++rr) {
                    const float x0 = frelu(acc[tm][tn][2*rr    ] + bn0);
                    const float x1 = frelu(acc[tm][tn][2*rr + 1] + bn1);
                    hh[(m + 8*rr) * 68 + (n >> 1)] =
                        pack2h(__float2half_rn(x0), __float2half_rn(x1));
                }
            }
        }
    }
    CP_ASYNC_WAIT0();
    __syncthreads();

    // =================== layer3: h2[128x128] @ W3[128x64] ===================
    float acc3[2][4][4];
    #pragma unroll
    for (int a = 0; a < 2; a++)
        #pragma unroll
        for (int b = 0; b < 4; b++)
            #pragma unroll
            for (int c = 0; c < 4; c++) acc3[a][b][c] = 0.0f;

    #pragma unroll
    for (int ks = 0; ks < 8; ++ks) {
        uint32_t afr[2][4];
        #pragma unroll
        for (int tm = 0; tm < 2; ++tm) {
            const int mrow = wm * 32 + tm * 16 + (lane & 7) + 8 * ((lane >> 3) & 1);
            const int kcol = ks * 16 + 8 * (lane >> 4);
            ldsm4(afr[tm], sb + SM_H2 + mrow * 272 + kcol * 2);
        }
        #pragma unroll
        for (int tp = 0; tp < 2; ++tp) {
            uint32_t bh[4];
            const int nrow = wn * 32 + tp * 16 + (lane & 7) + 8 * (lane >> 4);
            const int kcol = ks * 16 + 8 * ((lane >> 3) & 1);
            ldsm4(bh, sb + SM_W3 + nrow * 272 + kcol * 2);
            #pragma unroll
            for (int tm = 0; tm < 2; ++tm) {
                mma_f16(acc3[tm][2*tp    ], afr[tm], &bh[0]);
                mma_f16(acc3[tm][2*tp + 1], afr[tm], &bh[2]);
            }
        }
    }

    // ============== layer3 epilogue + layer4 (registers + shfl) =============
    float part[4] = {0.0f, 0.0f, 0.0f, 0.0f};   // rows: tm*16 + rr*8 + (lane>>2)
    #pragma unroll
    for (int tn = 0; tn < 4; ++tn) {
        const int n = wn * 32 + tn * 8 + (lane & 3) * 2;
        const float bn0 = b3s[n], bn1 = b3s[n + 1];
        const float w0 = W4s[n],  w1 = W4s[n + 1];
        #pragma unroll
        for (int tm = 0; tm < 2; ++tm) {
            #pragma unroll
            for (int rr = 0; rr < 2; ++rr) {
                part[tm*2 + rr] += frelu(acc3[tm][tn][2*rr    ] + bn0) * w0
                                 + frelu(acc3[tm][tn][2*rr + 1] + bn1) * w1;
            }
        }
    }
    #pragma unroll
    for (int i = 0; i < 4; ++i) {
        part[i] += __shfl_xor_sync(0xffffffffu, part[i], 1);
        part[i] += __shfl_xor_sync(0xffffffffu, part[i], 2);
    }
    if ((lane & 3) == 0) {
        #pragma unroll
        for (int tm = 0; tm < 2; ++tm)
            #pragma unroll
            for (int rr = 0; rr < 2; ++rr) {
                const int m = wm * 32 + tm * 16 + rr * 8 + (lane >> 2);
                red[wn * 128 + m] = part[tm*2 + rr];
            }
    }
    __syncthreads();
    if (tid < 128) {
        const float v = red[tid] + red[128 + tid] + b4[0];
        out[(q0 + tid) * NS + s_idx] = 1.0f / (1.0f + expf(-v));
    }
}

// ---------------------------------------------------------------------------
extern "C" void kernel_launch(void* const* d_in, const int* in_sizes, int n_in,
                              void* d_out, int out_size)
{
    const float* qf = (const float*)d_in[0];
    const float* sf = (const float*)d_in[1];
    // d_in[2] = support_y (unused)
    const float* W1 = (const float*)d_in[3];
    const float* b1 = (const float*)d_in[4];
    const float* W2 = (const float*)d_in[5];
    const float* b2 = (const float*)d_in[6];
    const float* W3 = (const float*)d_in[7];
    const float* b3 = (const float*)d_in[8];
    const float* W4 = (const float*)d_in[9];
    const float* b4 = (const float*)d_in[10];
    float* out = (float*)d_out;

    cudaFuncSetAttribute(relation_mma_kernel,
                         cudaFuncAttributeMaxDynamicSharedMemorySize, SMEM_TOTAL);
    cudaFuncSetAttribute(precompute_mma_kernel,
                         cudaFuncAttributeMaxDynamicSharedMemorySize, PRE_SMEM_TOTAL);

    prep_weights_kernel<<<640, 256>>>(W1, W2, W3);
    precompute_mma_kernel<<<dim3(10, 2), 256, PRE_SMEM_TOTAL>>>(qf, sf, b1);
    relation_mma_kernel<<<dim3(NS, NQ / TM), 256, SMEM_TOTAL>>>(b2, b3, W4, b4, out);
}

// round 8
// speedup vs baseline: 6.3330x; 1.3333x over previous
#include <cuda_runtime.h>
#include <cuda_fp16.h>
#include <math.h>
#include <stdint.h>

#define NQ 1024
#define NS 256
#define E  256
#define H1 256
#define H2 128
#define H3 64
#define TM 128          // query rows per CTA

// ---------------- warp-MMA helpers (plain sm_80+ PTX) -----------------------
__device__ __forceinline__ uint32_t smem_to_u32(const void* p) {
    uint32_t a;
    asm("{ .reg .u64 t; cvta.to.shared.u64 t, %1; cvt.u32.u64 %0, t; }" : "=r"(a) : "l"(p));
    return a;
}
__device__ __forceinline__ void ldsm4(uint32_t* r, uint32_t addr) {
    asm volatile("ldmatrix.sync.aligned.m8n8.x4.shared.b16 {%0,%1,%2,%3}, [%4];"
                 : "=r"(r[0]), "=r"(r[1]), "=r"(r[2]), "=r"(r[3]) : "r"(addr));
}
__device__ __forceinline__ void mma_f16(float* d, const uint32_t* a, const uint32_t* b) {
    asm volatile("mma.sync.aligned.m16n8k16.row.col.f32.f16.f16.f32 "
                 "{%0,%1,%2,%3}, {%4,%5,%6,%7}, {%8,%9}, {%0,%1,%2,%3};"
                 : "+f"(d[0]), "+f"(d[1]), "+f"(d[2]), "+f"(d[3])
                 : "r"(a[0]), "r"(a[1]), "r"(a[2]), "r"(a[3]), "r"(b[0]), "r"(b[1]));
}
__device__ __forceinline__ void cp_async16(uint32_t dst_smem, const void* src) {
    asm volatile("cp.async.cg.shared.global [%0], [%1], 16;"
                 :: "r"(dst_smem), "l"(src));
}
#define CP_ASYNC_COMMIT() asm volatile("cp.async.commit_group;" ::: "memory")
#define CP_ASYNC_WAIT0()  asm volatile("cp.async.wait_group 0;" ::: "memory")

__device__ __forceinline__ void split_f16(float x, __half& hi, __half& lo) {
    hi = __float2half_rn(x);
    lo = __float2half_rn(x - __half2float(hi));
}
__device__ __forceinline__ uint32_t pack2h(__half a, __half b) {
    __half2 t; t.x = a; t.y = b;
    return *reinterpret_cast<uint32_t*>(&t);
}
// relu(a + b) in packed fp16x2
__device__ __forceinline__ uint32_t hadd2_relu(uint32_t a, uint32_t b) {
    __half2 r = __hmax2(__hadd2(*reinterpret_cast<__half2*>(&a),
                                *reinterpret_cast<__half2*>(&b)),
                        __half2(__half(0.0f), __half(0.0f)));
    return *reinterpret_cast<uint32_t*>(&r);
}
__device__ __forceinline__ float frelu(float x) { return fmaxf(x, 0.0f); }

// ---------------- global scratch (static) -----------------------------------
// Qp stored as fp16 mma A-fragments: block (K16, M16) = 32 lanes x uint4;
// uint4 slots = {(g,t2),(g+8,t2),(g,t2+8),(g+8,t2+8)} pairs -> mma a-reg order.
__device__ uint4  g_QpF[16 * 64 * 32];        // [K16][M16][lane]
__device__ float  g_Sp [NS * H1];             // [s][k] (+b1)
__device__ __half g_W1TB_hi[163840];          // [(half*8+c)*256+n]*40+kk (kk<32)
__device__ __half g_W1TB_lo[163840];
__device__ __half g_W2TB[8][5120];            // [chunk][n*40+kk] fp16 (hi only)
__device__ __half g_W3TB[8704];               // [n*136+k] fp16 (hi only)

// ---------------- main-kernel smem layout (bytes) ----------------------------
#define SM_B2   0         // W2^T stage: 2 x 10240 = 20480
#define B2_STRIDE 10240
#define SM_W3   0         // phase B: W3^T [64n][136k] = 17408 (aliases SM_B2)
#define SM_H2   20480     // h2 fp16 [128m][136k] = 34816 (ends 55296)
#define SM_SP16 55296     // 256 fp16 = 512
#define SM_B2S  55808     // 128 f32
#define SM_B3S  56320     // 64 f32
#define SM_W4S  56576     // 64 f32
#define SM_RED  56832     // 2*128 f32 = 1024
#define SMEM_TOTAL 57856

// ---------------- precompute-kernel smem layout ------------------------------
#define PSM_A  0          // feat fp16 [128m][264k] = 67584
#define PSM_B  67584      // W1 stage: 2 x (hi 10240 + lo 10240) = 40960
#define PB_STRIDE 20480
#define PRE_SMEM_TOTAL 108544

// ---------------------------------------------------------------------------
// Weight prep: W1 -> fp16 hi/lo transposed+padded; W2/W3 -> fp16 (hi only)
// ---------------------------------------------------------------------------
__global__ void prep_weights_kernel(const float* __restrict__ W1,
                                    const float* __restrict__ W2,
                                    const float* __restrict__ W3)
{
    const int t = blockIdx.x * blockDim.x + threadIdx.x;   // 640*256 = 163840
    if (t < 163840) {
        const int kk = t % 40;
        const int n  = (t / 40) & 255;
        const int c  = (t / (40 * 256)) & 7;
        const int hf = t / (40 * 256 * 8);
        const float w = (kk < 32) ? W1[(hf * 256 + c * 32 + kk) * H1 + n] : 0.0f;
        __half hi, lo; split_f16(w, hi, lo);
        g_W1TB_hi[t] = hi;
        g_W1TB_lo[t] = lo;
    }
    if (t < 8 * 5120) {
        const int c = t / 5120, r = t % 5120;
        const int n = r / 40, kk = r % 40;
        const float w = (kk < 32) ? W2[(c * 32 + kk) * H2 + n] : 0.0f;
        g_W2TB[c][r] = __float2half_rn(w);
    }
    if (t < 8704) {
        const int n = t / 136, k = t % 136;
        const float w = (k < 128) ? W3[k * H3 + n] : 0.0f;
        g_W3TB[t] = __float2half_rn(w);
    }
}

// ---------------------------------------------------------------------------
// Precompute via mma: Qp -> fragment-layout fp16 (g_QpF); Sp -> fp32 (g_Sp).
// mb 0..7 -> Q blocks (128 rows), mb 8..9 -> S blocks; nb 0..1 (N=128).
// W1 staged hi+lo (2-term B split) so this step adds no fp16-weight error.
// ---------------------------------------------------------------------------
__global__ void __launch_bounds__(256)
precompute_mma_kernel(const float* __restrict__ qf,
                      const float* __restrict__ sf,
                      const float* __restrict__ b1)
{
    extern __shared__ char smem[];
    const uint32_t sb = smem_to_u32(smem);
    const int tid  = threadIdx.x;
    const int lane = tid & 31;
    const int wid  = tid >> 5;
    const int wm   = wid & 3;          // 4 warps along M
    const int wn   = wid >> 2;         // 2 warps along N
    const int mb   = blockIdx.x;       // 0..9
    const int nb   = blockIdx.y;       // 0..1
    const bool isQ = (mb < 8);
    const float* feat = isQ ? (qf + mb * 128 * E) : (sf + (mb - 8) * 128 * E);
    const int hf = isQ ? 0 : 1;

    // ---- stage A: feat[128][256] f32 -> fp16 smem [128][264] ----
    {
        const int row = tid >> 1, hv = tid & 1;
        const float4* src = reinterpret_cast<const float4*>(feat + row * E);
        uint32_t* dst = reinterpret_cast<uint32_t*>(smem + PSM_A);
        #pragma unroll 8
        for (int j = 0; j < 32; ++j) {
            const float4 v = src[hv * 32 + j];
            const int u = row * 132 + (hv * 32 + j) * 2;
            dst[u]     = pack2h(__float2half_rn(v.x), __float2half_rn(v.y));
            dst[u + 1] = pack2h(__float2half_rn(v.z), __float2half_rn(v.w));
        }
    }
    // ---- prologue: W1 chunk0 hi+lo via cp.async ----
    {
        const char* srcH = (const char*)&g_W1TB_hi[((hf * 8 + 0) * 256 + nb * 128) * 40];
        const char* srcL = (const char*)&g_W1TB_lo[((hf * 8 + 0) * 256 + nb * 128) * 40];
        const uint32_t dstH = sb + PSM_B;
        #pragma unroll
        for (int i = 0; i < 3; ++i) {
            const int t = tid + 256 * i;
            if (t < 640) {
                cp_async16(dstH + t * 16, srcH + t * 16);
                cp_async16(dstH + 10240 + t * 16, srcL + t * 16);
            }
        }
        CP_ASYNC_COMMIT();
    }
    __syncthreads();

    float acc[2][8][4];
    #pragma unroll
    for (int a = 0; a < 2; a++)
        #pragma unroll
        for (int b = 0; b < 8; b++)
            #pragma unroll
            for (int c = 0; c < 4; c++) acc[a][b][c] = 0.0f;

    for (int c = 0; c < 8; ++c) {
        const int st = c & 1;
        CP_ASYNC_WAIT0();
        __syncthreads();
        if (c < 7) {
            const int base = ((hf * 8 + c + 1) * 256 + nb * 128) * 40;
            const char* srcH = (const char*)&g_W1TB_hi[base];
            const char* srcL = (const char*)&g_W1TB_lo[base];
            const uint32_t dstH = sb + PSM_B + (st ^ 1) * PB_STRIDE;
            #pragma unroll
            for (int i = 0; i < 3; ++i) {
                const int t = tid + 256 * i;
                if (t < 640) {
                    cp_async16(dstH + t * 16, srcH + t * 16);
                    cp_async16(dstH + 10240 + t * 16, srcL + t * 16);
                }
            }
            CP_ASYNC_COMMIT();
        }
        const uint32_t bufH = sb + PSM_B + st * PB_STRIDE;
        #pragma unroll
        for (int ks = 0; ks < 2; ++ks) {
            uint32_t afr[2][4];
            #pragma unroll
            for (int tm = 0; tm < 2; ++tm) {
                const int mrow = wm * 32 + tm * 16 + (lane & 7) + 8 * ((lane >> 3) & 1);
                const int kcol = c * 32 + ks * 16 + 8 * (lane >> 4);
                ldsm4(afr[tm], sb + PSM_A + mrow * 528 + kcol * 2);
            }
            #pragma unroll
            for (int tp = 0; tp < 4; ++tp) {
                uint32_t bh[4], bl[4];
                const int nrow = wn * 64 + tp * 16 + (lane & 7) + 8 * (lane >> 4);
                const int kcol = ks * 16 + 8 * ((lane >> 3) & 1);
                const uint32_t baddr = bufH + nrow * 80 + kcol * 2;
                ldsm4(bh, baddr);
                ldsm4(bl, baddr + 10240);
                #pragma unroll
                for (int tm = 0; tm < 2; ++tm) {
                    mma_f16(acc[tm][2*tp    ], afr[tm], &bh[0]);
                    mma_f16(acc[tm][2*tp    ], afr[tm], &bl[0]);
                    mma_f16(acc[tm][2*tp + 1], afr[tm], &bh[2]);
                    mma_f16(acc[tm][2*tp + 1], afr[tm], &bl[2]);
                }
            }
        }
    }

    // ---- epilogue ----
    if (isQ) {
        // Emit fp16 A-fragments. D-fragment lane mapping == A-fragment lane
        // mapping, so each thread packs its own acc values; fully coalesced.
        #pragma unroll
        for (int tm = 0; tm < 2; ++tm)
            #pragma unroll
            for (int tnp = 0; tnp < 4; ++tnp) {
                const int K16 = nb * 8 + wn * 4 + tnp;
                const int M16 = mb * 8 + wm * 2 + tm;
                uint4 v;
                v.x = pack2h(__float2half_rn(acc[tm][2*tnp][0]),
                             __float2half_rn(acc[tm][2*tnp][1]));
                v.y = pack2h(__float2half_rn(acc[tm][2*tnp][2]),
                             __float2half_rn(acc[tm][2*tnp][3]));
                v.z = pack2h(__float2half_rn(acc[tm][2*tnp+1][0]),
                             __float2half_rn(acc[tm][2*tnp+1][1]));
                v.w = pack2h(__float2half_rn(acc[tm][2*tnp+1][2]),
                             __float2half_rn(acc[tm][2*tnp+1][3]));
                g_QpF[(K16 * 64 + M16) * 32 + lane] = v;
            }
    } else {
        const int s0 = (mb - 8) * 128;
        #pragma unroll
        for (int tm = 0; tm < 2; ++tm)
            #pragma unroll
            for (int tn = 0; tn < 8; ++tn) {
                const int n = nb * 128 + wn * 64 + tn * 8 + (lane & 3) * 2;
                const float bb0 = b1[n], bb1 = b1[n + 1];
                #pragma unroll
                for (int rr = 0; rr < 2; ++rr) {
                    const int m = wm * 32 + tm * 16 + rr * 8 + (lane >> 2);
                    g_Sp[(s0 + m) * H1 + n]     = acc[tm][tn][2*rr]     + bb0;
                    g_Sp[(s0 + m) * H1 + n + 1] = acc[tm][tn][2*rr + 1] + bb1;
                }
            }
    }
}

// ---------------------------------------------------------------------------
// Fused MLP: one CTA = 128 q-pairs x 1 support; layers 2..4 via mma.sync f16.
// R7: A built fully in registers from fragment-layout Qp (LDG.128 + HADD2 +
// HMAX2); no A smem, no A ldmatrix, one sync per chunk.
// ---------------------------------------------------------------------------
__global__ void __launch_bounds__(256, 2)
relation_mma_kernel(const float* __restrict__ b2,
                    const float* __restrict__ b3,
                    const float* __restrict__ W4,
                    const float* __restrict__ b4,
                    float* __restrict__ out)
{
    extern __shared__ char smem[];
    const uint32_t sb = smem_to_u32(smem);
    const int tid  = threadIdx.x;
    const int lane = tid & 31;
    const int wid  = tid >> 5;
    const int wm   = wid & 3;          // 4 warps along M
    const int wn   = wid >> 2;         // 2 warps along N
    const int s_idx = blockIdx.x;
    const int q0    = blockIdx.y * TM;
    const int M16b  = blockIdx.y * 8 + wm * 2;   // global m16-tile base for warp

    float* b2s = (float*)(smem + SM_B2S);
    float* b3s = (float*)(smem + SM_B3S);
    float* W4s = (float*)(smem + SM_W4S);
    float* red = (float*)(smem + SM_RED);
    __half* sp16 = (__half*)(smem + SM_SP16);

    sp16[tid] = __float2half_rn(g_Sp[s_idx * H1 + tid]);
    if (tid < H2) b2s[tid] = b2[tid];
    if (tid < H3) { b3s[tid] = b3[tid]; W4s[tid] = W4[tid]; }

    // ---- prologue: cp.async W2 chunk0; LDG A fragments chunk0 ----
    {
        const char* srcH = (const char*)g_W2TB[0];
        const uint32_t dstH = sb + SM_B2;
        #pragma unroll
        for (int i = 0; i < 3; ++i) {
            const int t = tid + 256 * i;
            if (t < 640) cp_async16(dstH + t * 16, srcH + t * 16);
        }
        CP_ASYNC_COMMIT();
    }
    uint4 aq[2][2];   // [tm][ks] raw Qp fragments for current chunk
    #pragma unroll
    for (int tm = 0; tm < 2; ++tm)
        #pragma unroll
        for (int ks = 0; ks < 2; ++ks)
            aq[tm][ks] = g_QpF[(ks * 64 + M16b + tm) * 32 + lane];

    float acc[2][8][4];
    #pragma unroll
    for (int a = 0; a < 2; a++)
        #pragma unroll
        for (int b = 0; b < 8; b++)
            #pragma unroll
            for (int c = 0; c < 4; c++) acc[a][b][c] = 0.0f;

    // =================== layer2 mainloop: 8 chunks of k=32 ==================
    for (int c = 0; c < 8; ++c) {
        const int st = c & 1;
        CP_ASYNC_WAIT0();      // W2 chunk c arrived
        __syncthreads();       // B buf[st] visible; prior reads of buf[st] done

        // A fragments: relu(Qp + Sp) in packed fp16 registers
        uint32_t af[2][2][4];  // [tm][ks][reg]
        #pragma unroll
        for (int ks = 0; ks < 2; ++ks) {
            const uint32_t spA = *(const uint32_t*)(smem + SM_SP16 + c * 64 + ks * 32 + (lane & 3) * 4);
            const uint32_t spB = *(const uint32_t*)(smem + SM_SP16 + c * 64 + ks * 32 + (lane & 3) * 4 + 16);
            #pragma unroll
            for (int tm = 0; tm < 2; ++tm) {
                af[tm][ks][0] = hadd2_relu(aq[tm][ks].x, spA);
                af[tm][ks][1] = hadd2_relu(aq[tm][ks].y, spA);
                af[tm][ks][2] = hadd2_relu(aq[tm][ks].z, spB);
                af[tm][ks][3] = hadd2_relu(aq[tm][ks].w, spB);
            }
        }
        if (c < 7) {
            // prefetch A fragments for chunk c+1 (hidden under mma below)
            #pragma unroll
            for (int tm = 0; tm < 2; ++tm)
                #pragma unroll
                for (int ks = 0; ks < 2; ++ks)
                    aq[tm][ks] = g_QpF[(((c + 1) * 2 + ks) * 64 + M16b + tm) * 32 + lane];
            // stage W2 chunk c+1 into the other buffer
            const char* srcH = (const char*)g_W2TB[c + 1];
            const uint32_t dstH = sb + SM_B2 + (st ^ 1) * B2_STRIDE;
            #pragma unroll
            for (int i = 0; i < 3; ++i) {
                const int t = tid + 256 * i;
                if (t < 640) cp_async16(dstH + t * 16, srcH + t * 16);
            }
            CP_ASYNC_COMMIT();
        }

        // mma phase
        const uint32_t b2b = sb + SM_B2 + st * B2_STRIDE;
        #pragma unroll
        for (int ks = 0; ks < 2; ++ks) {
            #pragma unroll
            for (int tp = 0; tp < 4; ++tp) {
                uint32_t bh[4];
                const int nrow = wn * 64 + tp * 16 + (lane & 7) + 8 * (lane >> 4);
                const int kcol = ks * 16 + 8 * ((lane >> 3) & 1);
                ldsm4(bh, b2b + nrow * 80 + kcol * 2);
                #pragma unroll
                for (int tm = 0; tm < 2; ++tm) {
                    mma_f16(acc[tm][2*tp    ], af[tm][ks], &bh[0]);
                    mma_f16(acc[tm][2*tp + 1], af[tm][ks], &bh[2]);
                }
            }
        }
    }
    __syncthreads();   // all mainloop smem reads done; B2 buffers dead

    // stage whole W3^T via cp.async (overlaps with epilogue below)
    {
        const char* srcH = (const char*)g_W3TB;
        #pragma unroll
        for (int i = 0; i < 5; ++i) {
            const int t = tid + 256 * i;
            if (t < 1088) cp_async16(sb + SM_W3 + t * 16, srcH + t * 16);
        }
        CP_ASYNC_COMMIT();
    }
    // layer2 epilogue: bias+relu -> fp16 -> h2[m][k] (packed u32 stores)
    {
        uint32_t* hh = reinterpret_cast<uint32_t*>(smem + SM_H2);
        #pragma unroll
        for (int tm = 0; tm < 2; ++tm) {
            #pragma unroll
            for (int tn = 0; tn < 8; ++tn) {
                const int n = wn * 64 + tn * 8 + (lane & 3) * 2;
                const int m = wm * 32 + tm * 16 + (lane >> 2);
                const float bn0 = b2s[n], bn1 = b2s[n + 1];
                #pragma unroll
                for (int rr = 0; rr < 2; ++rr) {
                    const float x0 = frelu(acc[tm][tn][2*rr    ] + bn0);
                    const float x1 = frelu(acc[tm][tn][2*rr + 1] + bn1);
                    hh[(m + 8*rr) * 68 + (n >> 1)] =
                        pack2h(__float2half_rn(x0), __float2half_rn(x1));
                }
            }
        }
    }
    CP_ASYNC_WAIT0();
    __syncthreads();

    // =================== layer3: h2[128x128] @ W3[128x64] ===================
    float acc3[2][4][4];
    #pragma unroll
    for (int a = 0; a < 2; a++)
        #pragma unroll
        for (int b = 0; b < 4; b++)
            #pragma unroll
            for (int c = 0; c < 4; c++) acc3[a][b][c] = 0.0f;

    #pragma unroll
    for (int ks = 0; ks < 8; ++ks) {
        uint32_t afr[2][4];
        #pragma unroll
        for (int tm = 0; tm < 2; ++tm) {
            const int mrow = wm * 32 + tm * 16 + (lane & 7) + 8 * ((lane >> 3) & 1);
            const int kcol = ks * 16 + 8 * (lane >> 4);
            ldsm4(afr[tm], sb + SM_H2 + mrow * 272 + kcol * 2);
        }
        #pragma unroll
        for (int tp = 0; tp < 2; ++tp) {
            uint32_t bh[4];
            const int nrow = wn * 32 + tp * 16 + (lane & 7) + 8 * (lane >> 4);
            const int kcol = ks * 16 + 8 * ((lane >> 3) & 1);
            ldsm4(bh, sb + SM_W3 + nrow * 272 + kcol * 2);
            #pragma unroll
            for (int tm = 0; tm < 2; ++tm) {
                mma_f16(acc3[tm][2*tp    ], afr[tm], &bh[0]);
                mma_f16(acc3[tm][2*tp + 1], afr[tm], &bh[2]);
            }
        }
    }

    // ============== layer3 epilogue + layer4 (registers + shfl) =============
    float part[4] = {0.0f, 0.0f, 0.0f, 0.0f};   // rows: tm*16 + rr*8 + (lane>>2)
    #pragma unroll
    for (int tn = 0; tn < 4; ++tn) {
        const int n = wn * 32 + tn * 8 + (lane & 3) * 2;
        const float bn0 = b3s[n], bn1 = b3s[n + 1];
        const float w0 = W4s[n],  w1 = W4s[n + 1];
        #pragma unroll
        for (int tm = 0; tm < 2; ++tm) {
            #pragma unroll
            for (int rr = 0; rr < 2; ++rr) {
                part[tm*2 + rr] += frelu(acc3[tm][tn][2*rr    ] + bn0) * w0
                                 + frelu(acc3[tm][tn][2*rr + 1] + bn1) * w1;
            }
        }
    }
    #pragma unroll
    for (int i = 0; i < 4; ++i) {
        part[i] += __shfl_xor_sync(0xffffffffu, part[i], 1);
        part[i] += __shfl_xor_sync(0xffffffffu, part[i], 2);
    }
    if ((lane & 3) == 0) {
        #pragma unroll
        for (int tm = 0; tm < 2; ++tm)
            #pragma unroll
            for (int rr = 0; rr < 2; ++rr) {
                const int m = wm * 32 + tm * 16 + rr * 8 + (lane >> 2);
                red[wn * 128 + m] = part[tm*2 + rr];
            }
    }
    __syncthreads();
    if (tid < 128) {
        const float v = red[tid] + red[128 + tid] + b4[0];
        out[(q0 + tid) * NS + s_idx] = 1.0f / (1.0f + expf(-v));
    }
}

// ---------------------------------------------------------------------------
extern "C" void kernel_launch(void* const* d_in, const int* in_sizes, int n_in,
                              void* d_out, int out_size)
{
    const float* qf = (const float*)d_in[0];
    const float* sf = (const float*)d_in[1];
    // d_in[2] = support_y (unused)
    const float* W1 = (const float*)d_in[3];
    const float* b1 = (const float*)d_in[4];
    const float* W2 = (const float*)d_in[5];
    const float* b2 = (const float*)d_in[6];
    const float* W3 = (const float*)d_in[7];
    const float* b3 = (const float*)d_in[8];
    const float* W4 = (const float*)d_in[9];
    const float* b4 = (const float*)d_in[10];
    float* out = (float*)d_out;

    cudaFuncSetAttribute(relation_mma_kernel,
                         cudaFuncAttributeMaxDynamicSharedMemorySize, SMEM_TOTAL);
    cudaFuncSetAttribute(precompute_mma_kernel,
                         cudaFuncAttributeMaxDynamicSharedMemorySize, PRE_SMEM_TOTAL);

    prep_weights_kernel<<<640, 256>>>(W1, W2, W3);
    precompute_mma_kernel<<<dim3(10, 2), 256, PRE_SMEM_TOTAL>>>(qf, sf, b1);
    relation_mma_kernel<<<dim3(NS, NQ / TM), 256, SMEM_TOTAL>>>(b2, b3, W4, b4, out);
}

// round 9
// speedup vs baseline: 6.9271x; 1.0938x over previous
#include <cuda_runtime.h>
#include <cuda_fp16.h>
#include <math.h>
#include <stdint.h>

#define NQ 1024
#define NS 256
#define E  256
#define H1 256
#define H2 128
#define H3 64
#define TM 128          // query rows per CTA

// ---------------- warp-MMA helpers (plain sm_80+ PTX) -----------------------
__device__ __forceinline__ uint32_t smem_to_u32(const void* p) {
    uint32_t a;
    asm("{ .reg .u64 t; cvta.to.shared.u64 t, %1; cvt.u32.u64 %0, t; }" : "=r"(a) : "l"(p));
    return a;
}
__device__ __forceinline__ void ldsm4(uint32_t* r, uint32_t addr) {
    asm volatile("ldmatrix.sync.aligned.m8n8.x4.shared.b16 {%0,%1,%2,%3}, [%4];"
                 : "=r"(r[0]), "=r"(r[1]), "=r"(r[2]), "=r"(r[3]) : "r"(addr));
}
__device__ __forceinline__ void mma_f16(float* d, const uint32_t* a, const uint32_t* b) {
    asm volatile("mma.sync.aligned.m16n8k16.row.col.f32.f16.f16.f32 "
                 "{%0,%1,%2,%3}, {%4,%5,%6,%7}, {%8,%9}, {%0,%1,%2,%3};"
                 : "+f"(d[0]), "+f"(d[1]), "+f"(d[2]), "+f"(d[3])
                 : "r"(a[0]), "r"(a[1]), "r"(a[2]), "r"(a[3]), "r"(b[0]), "r"(b[1]));
}
__device__ __forceinline__ void cp_async16(uint32_t dst_smem, const void* src) {
    asm volatile("cp.async.cg.shared.global [%0], [%1], 16;"
                 :: "r"(dst_smem), "l"(src));
}
#define CP_ASYNC_COMMIT() asm volatile("cp.async.commit_group;" ::: "memory")
#define CP_ASYNC_WAIT0()  asm volatile("cp.async.wait_group 0;" ::: "memory")

__device__ __forceinline__ void split_f16(float x, __half& hi, __half& lo) {
    hi = __float2half_rn(x);
    lo = __float2half_rn(x - __half2float(hi));
}
__device__ __forceinline__ uint32_t pack2h(__half a, __half b) {
    __half2 t; t.x = a; t.y = b;
    return *reinterpret_cast<uint32_t*>(&t);
}
// relu(a + b) in packed fp16x2
__device__ __forceinline__ uint32_t hadd2_relu(uint32_t a, uint32_t b) {
    __half2 r = __hmax2(__hadd2(*reinterpret_cast<__half2*>(&a),
                                *reinterpret_cast<__half2*>(&b)),
                        __half2(__half(0.0f), __half(0.0f)));
    return *reinterpret_cast<uint32_t*>(&r);
}
__device__ __forceinline__ float frelu(float x) { return fmaxf(x, 0.0f); }

// ---------------- global scratch (static) -----------------------------------
// Qp stored as fp16 mma A-fragments: block (K16, M16) = 32 lanes x uint4.
__device__ uint4  g_QpF[16 * 64 * 32];        // [K16][M16][lane]
__device__ float  g_Sp [NS * H1];             // [s][k] (+b1)
__device__ __half g_W1TB_hi[163840];          // [(half*8+c)*256+n]*40+kk (kk<32)
__device__ __half g_W1TB_lo[163840];
__device__ __half g_W2TB[128 * 264];          // [n][264k] fp16, k<256 data
__device__ __half g_W3TB[8704];               // [n*136+k] fp16

// ---------------- main-kernel smem layout (bytes) ----------------------------
#define SM_W2   0         // whole W2^T [128n][264k] fp16 = 67584
#define SM_W3   0         // phase B: W3^T [64n][136k] = 17408 (aliases SM_W2)
#define SM_H2   67584     // h2 fp16 [128m][136k] = 34816 (ends 102400)
#define SM_SP16 102400    // 256 fp16 = 512
#define SM_B2S  102912    // 128 f32
#define SM_B3S  103424    // 64 f32
#define SM_W4S  103680    // 64 f32
#define SM_RED  103936    // 2*128 f32 = 1024
#define SMEM_TOTAL 104960

// ---------------- precompute-kernel smem layout ------------------------------
#define PSM_A  0          // feat fp16 [128m][264k] = 67584
#define PSM_B  67584      // W1 stage: 2 x (hi 10240 + lo 10240) = 40960
#define PB_STRIDE 20480
#define PRE_SMEM_TOTAL 108544

// ---------------------------------------------------------------------------
// Weight prep: W1 -> fp16 hi/lo transposed+padded; W2 -> [n][264] fp16; W3.
// ---------------------------------------------------------------------------
__global__ void prep_weights_kernel(const float* __restrict__ W1,
                                    const float* __restrict__ W2,
                                    const float* __restrict__ W3)
{
    const int t = blockIdx.x * blockDim.x + threadIdx.x;   // 640*256 = 163840
    if (t < 163840) {
        const int kk = t % 40;
        const int n  = (t / 40) & 255;
        const int c  = (t / (40 * 256)) & 7;
        const int hf = t / (40 * 256 * 8);
        const float w = (kk < 32) ? W1[(hf * 256 + c * 32 + kk) * H1 + n] : 0.0f;
        __half hi, lo; split_f16(w, hi, lo);
        g_W1TB_hi[t] = hi;
        g_W1TB_lo[t] = lo;
    }
    if (t < 128 * 264) {
        const int n = t / 264, k = t % 264;
        const float w = (k < 256) ? W2[k * H2 + n] : 0.0f;
        g_W2TB[t] = __float2half_rn(w);
    }
    if (t < 8704) {
        const int n = t / 136, k = t % 136;
        const float w = (k < 128) ? W3[k * H3 + n] : 0.0f;
        g_W3TB[t] = __float2half_rn(w);
    }
}

// ---------------------------------------------------------------------------
// Precompute via mma: Qp -> fragment-layout fp16 (g_QpF); Sp -> fp32 (g_Sp).
// ---------------------------------------------------------------------------
__global__ void __launch_bounds__(256)
precompute_mma_kernel(const float* __restrict__ qf,
                      const float* __restrict__ sf,
                      const float* __restrict__ b1)
{
    extern __shared__ char smem[];
    const uint32_t sb = smem_to_u32(smem);
    const int tid  = threadIdx.x;
    const int lane = tid & 31;
    const int wid  = tid >> 5;
    const int wm   = wid & 3;
    const int wn   = wid >> 2;
    const int mb   = blockIdx.x;       // 0..9
    const int nb   = blockIdx.y;       // 0..1
    const bool isQ = (mb < 8);
    const float* feat = isQ ? (qf + mb * 128 * E) : (sf + (mb - 8) * 128 * E);
    const int hf = isQ ? 0 : 1;

    // ---- stage A: feat[128][256] f32 -> fp16 smem [128][264] ----
    {
        const int row = tid >> 1, hv = tid & 1;
        const float4* src = reinterpret_cast<const float4*>(feat + row * E);
        uint32_t* dst = reinterpret_cast<uint32_t*>(smem + PSM_A);
        #pragma unroll 8
        for (int j = 0; j < 32; ++j) {
            const float4 v = src[hv * 32 + j];
            const int u = row * 132 + (hv * 32 + j) * 2;
            dst[u]     = pack2h(__float2half_rn(v.x), __float2half_rn(v.y));
            dst[u + 1] = pack2h(__float2half_rn(v.z), __float2half_rn(v.w));
        }
    }
    // ---- prologue: W1 chunk0 hi+lo via cp.async ----
    {
        const char* srcH = (const char*)&g_W1TB_hi[((hf * 8 + 0) * 256 + nb * 128) * 40];
        const char* srcL = (const char*)&g_W1TB_lo[((hf * 8 + 0) * 256 + nb * 128) * 40];
        const uint32_t dstH = sb + PSM_B;
        #pragma unroll
        for (int i = 0; i < 3; ++i) {
            const int t = tid + 256 * i;
            if (t < 640) {
                cp_async16(dstH + t * 16, srcH + t * 16);
                cp_async16(dstH + 10240 + t * 16, srcL + t * 16);
            }
        }
        CP_ASYNC_COMMIT();
    }
    __syncthreads();

    float acc[2][8][4];
    #pragma unroll
    for (int a = 0; a < 2; a++)
        #pragma unroll
        for (int b = 0; b < 8; b++)
            #pragma unroll
            for (int c = 0; c < 4; c++) acc[a][b][c] = 0.0f;

    for (int c = 0; c < 8; ++c) {
        const int st = c & 1;
        CP_ASYNC_WAIT0();
        __syncthreads();
        if (c < 7) {
            const int base = ((hf * 8 + c + 1) * 256 + nb * 128) * 40;
            const char* srcH = (const char*)&g_W1TB_hi[base];
            const char* srcL = (const char*)&g_W1TB_lo[base];
            const uint32_t dstH = sb + PSM_B + (st ^ 1) * PB_STRIDE;
            #pragma unroll
            for (int i = 0; i < 3; ++i) {
                const int t = tid + 256 * i;
                if (t < 640) {
                    cp_async16(dstH + t * 16, srcH + t * 16);
                    cp_async16(dstH + 10240 + t * 16, srcL + t * 16);
                }
            }
            CP_ASYNC_COMMIT();
        }
        const uint32_t bufH = sb + PSM_B + st * PB_STRIDE;
        #pragma unroll
        for (int ks = 0; ks < 2; ++ks) {
            uint32_t afr[2][4];
            #pragma unroll
            for (int tm = 0; tm < 2; ++tm) {
                const int mrow = wm * 32 + tm * 16 + (lane & 7) + 8 * ((lane >> 3) & 1);
                const int kcol = c * 32 + ks * 16 + 8 * (lane >> 4);
                ldsm4(afr[tm], sb + PSM_A + mrow * 528 + kcol * 2);
            }
            #pragma unroll
            for (int tp = 0; tp < 4; ++tp) {
                uint32_t bh[4], bl[4];
                const int nrow = wn * 64 + tp * 16 + (lane & 7) + 8 * (lane >> 4);
                const int kcol = ks * 16 + 8 * ((lane >> 3) & 1);
                const uint32_t baddr = bufH + nrow * 80 + kcol * 2;
                ldsm4(bh, baddr);
                ldsm4(bl, baddr + 10240);
                #pragma unroll
                for (int tm = 0; tm < 2; ++tm) {
                    mma_f16(acc[tm][2*tp    ], afr[tm], &bh[0]);
                    mma_f16(acc[tm][2*tp    ], afr[tm], &bl[0]);
                    mma_f16(acc[tm][2*tp + 1], afr[tm], &bh[2]);
                    mma_f16(acc[tm][2*tp + 1], afr[tm], &bl[2]);
                }
            }
        }
    }

    // ---- epilogue ----
    if (isQ) {
        #pragma unroll
        for (int tm = 0; tm < 2; ++tm)
            #pragma unroll
            for (int tnp = 0; tnp < 4; ++tnp) {
                const int K16 = nb * 8 + wn * 4 + tnp;
                const int M16 = mb * 8 + wm * 2 + tm;
                uint4 v;
                v.x = pack2h(__float2half_rn(acc[tm][2*tnp][0]),
                             __float2half_rn(acc[tm][2*tnp][1]));
                v.y = pack2h(__float2half_rn(acc[tm][2*tnp][2]),
                             __float2half_rn(acc[tm][2*tnp][3]));
                v.z = pack2h(__float2half_rn(acc[tm][2*tnp+1][0]),
                             __float2half_rn(acc[tm][2*tnp+1][1]));
                v.w = pack2h(__float2half_rn(acc[tm][2*tnp+1][2]),
                             __float2half_rn(acc[tm][2*tnp+1][3]));
                g_QpF[(K16 * 64 + M16) * 32 + lane] = v;
            }
    } else {
        const int s0 = (mb - 8) * 128;
        #pragma unroll
        for (int tm = 0; tm < 2; ++tm)
            #pragma unroll
            for (int tn = 0; tn < 8; ++tn) {
                const int n = nb * 128 + wn * 64 + tn * 8 + (lane & 3) * 2;
                const float bb0 = b1[n], bb1 = b1[n + 1];
                #pragma unroll
                for (int rr = 0; rr < 2; ++rr) {
                    const int m = wm * 32 + tm * 16 + rr * 8 + (lane >> 2);
                    g_Sp[(s0 + m) * H1 + n]     = acc[tm][tn][2*rr]     + bb0;
                    g_Sp[(s0 + m) * H1 + n + 1] = acc[tm][tn][2*rr + 1] + bb1;
                }
            }
    }
}

// ---------------------------------------------------------------------------
// Fused MLP. R8: whole W2 staged once; layer2 mainloop has ZERO barriers and
// zero cp.async -- pure LDG/LDS/HADD2/ldsm/mma, pipelined across chunks.
// ---------------------------------------------------------------------------
__global__ void __launch_bounds__(256, 2)
relation_mma_kernel(const float* __restrict__ b2,
                    const float* __restrict__ b3,
                    const float* __restrict__ W4,
                    const float* __restrict__ b4,
                    float* __restrict__ out)
{
    extern __shared__ char smem[];
    const uint32_t sb = smem_to_u32(smem);
    const int tid  = threadIdx.x;
    const int lane = tid & 31;
    const int wid  = tid >> 5;
    const int wm   = wid & 3;          // 4 warps along M
    const int wn   = wid >> 2;         // 2 warps along N
    const int s_idx = blockIdx.x;
    const int q0    = blockIdx.y * TM;
    const int M16b  = blockIdx.y * 8 + wm * 2;

    float* b2s = (float*)(smem + SM_B2S);
    float* b3s = (float*)(smem + SM_B3S);
    float* W4s = (float*)(smem + SM_W4S);
    float* red = (float*)(smem + SM_RED);
    __half* sp16 = (__half*)(smem + SM_SP16);

    sp16[tid] = __float2half_rn(g_Sp[s_idx * H1 + tid]);
    if (tid < H2) b2s[tid] = b2[tid];
    if (tid < H3) { b3s[tid] = b3[tid]; W4s[tid] = W4[tid]; }

    // ---- prologue: cp.async the WHOLE W2 (67584 B = 4224 x 16B) ----
    {
        const char* src = (const char*)g_W2TB;
        #pragma unroll
        for (int i = 0; i < 17; ++i) {
            const int t = tid + 256 * i;
            if (t < 4224) cp_async16(sb + SM_W2 + t * 16, src + t * 16);
        }
        CP_ASYNC_COMMIT();
    }
    uint4 aq[2][2];   // [tm][ks] raw Qp fragments for current chunk
    #pragma unroll
    for (int tm = 0; tm < 2; ++tm)
        #pragma unroll
        for (int ks = 0; ks < 2; ++ks)
            aq[tm][ks] = g_QpF[(ks * 64 + M16b + tm) * 32 + lane];

    float acc[2][8][4];
    #pragma unroll
    for (int a = 0; a < 2; a++)
        #pragma unroll
        for (int b = 0; b < 8; b++)
            #pragma unroll
            for (int c = 0; c < 4; c++) acc[a][b][c] = 0.0f;

    CP_ASYNC_WAIT0();
    __syncthreads();   // W2 + sp16 + biases visible; ONLY barrier before loop

    // ============ layer2 mainloop: 8 chunks of k=32, barrier-free ===========
    #pragma unroll
    for (int c = 0; c < 8; ++c) {
        // A fragments: relu(Qp + Sp) in packed fp16 registers
        uint32_t af[2][2][4];
        #pragma unroll
        for (int ks = 0; ks < 2; ++ks) {
            const uint32_t spA = *(const uint32_t*)(smem + SM_SP16 + c * 64 + ks * 32 + (lane & 3) * 4);
            const uint32_t spB = *(const uint32_t*)(smem + SM_SP16 + c * 64 + ks * 32 + (lane & 3) * 4 + 16);
            #pragma unroll
            for (int tm = 0; tm < 2; ++tm) {
                af[tm][ks][0] = hadd2_relu(aq[tm][ks].x, spA);
                af[tm][ks][1] = hadd2_relu(aq[tm][ks].y, spA);
                af[tm][ks][2] = hadd2_relu(aq[tm][ks].z, spB);
                af[tm][ks][3] = hadd2_relu(aq[tm][ks].w, spB);
            }
        }
        if (c < 7) {   // prefetch next chunk's Qp fragments (hidden under mma)
            #pragma unroll
            for (int tm = 0; tm < 2; ++tm)
                #pragma unroll
                for (int ks = 0; ks < 2; ++ks)
                    aq[tm][ks] = g_QpF[(((c + 1) * 2 + ks) * 64 + M16b + tm) * 32 + lane];
        }
        // mma phase: B from resident W2 smem (read-only, no sync needed)
        #pragma unroll
        for (int ks = 0; ks < 2; ++ks) {
            #pragma unroll
            for (int tp = 0; tp < 4; ++tp) {
                uint32_t bh[4];
                const int nrow = wn * 64 + tp * 16 + (lane & 7) + 8 * (lane >> 4);
                const int kcol = c * 32 + ks * 16 + 8 * ((lane >> 3) & 1);
                ldsm4(bh, sb + SM_W2 + nrow * 528 + kcol * 2);
                #pragma unroll
                for (int tm = 0; tm < 2; ++tm) {
                    mma_f16(acc[tm][2*tp    ], af[tm][ks], &bh[0]);
                    mma_f16(acc[tm][2*tp + 1], af[tm][ks], &bh[2]);
                }
            }
        }
    }
    __syncthreads();   // all W2 reads done CTA-wide; W2 region reusable

    // stage W3^T into W2's region via cp.async (overlaps epilogue below)
    {
        const char* srcH = (const char*)g_W3TB;
        #pragma unroll
        for (int i = 0; i < 5; ++i) {
            const int t = tid + 256 * i;
            if (t < 1088) cp_async16(sb + SM_W3 + t * 16, srcH + t * 16);
        }
        CP_ASYNC_COMMIT();
    }
    // layer2 epilogue: bias+relu -> fp16 -> h2[m][k]
    {
        uint32_t* hh = reinterpret_cast<uint32_t*>(smem + SM_H2);
        #pragma unroll
        for (int tm = 0; tm < 2; ++tm) {
            #pragma unroll
            for (int tn = 0; tn < 8; ++tn) {
                const int n = wn * 64 + tn * 8 + (lane & 3) * 2;
                const int m = wm * 32 + tm * 16 + (lane >> 2);
                const float bn0 = b2s[n], bn1 = b2s[n + 1];
                #pragma unroll
                for (int rr = 0; rr < 2; ++rr) {
                    const float x0 = frelu(acc[tm][tn][2*rr    ] + bn0);
                    const float x1 = frelu(acc[tm][tn][2*rr + 1] + bn1);
                    hh[(m + 8*rr) * 68 + (n >> 1)] =
                        pack2h(__float2half_rn(x0), __float2half_rn(x1));
                }
            }
        }
    }
    CP_ASYNC_WAIT0();
    __syncthreads();

    // =================== layer3: h2[128x128] @ W3[128x64] ===================
    float acc3[2][4][4];
    #pragma unroll
    for (int a = 0; a < 2; a++)
        #pragma unroll
        for (int b = 0; b < 4; b++)
            #pragma unroll
            for (int c = 0; c < 4; c++) acc3[a][b][c] = 0.0f;

    #pragma unroll
    for (int ks = 0; ks < 8; ++ks) {
        uint32_t afr[2][4];
        #pragma unroll
        for (int tm = 0; tm < 2; ++tm) {
            const int mrow = wm * 32 + tm * 16 + (lane & 7) + 8 * ((lane >> 3) & 1);
            const int kcol = ks * 16 + 8 * (lane >> 4);
            ldsm4(afr[tm], sb + SM_H2 + mrow * 272 + kcol * 2);
        }
        #pragma unroll
        for (int tp = 0; tp < 2; ++tp) {
            uint32_t bh[4];
            const int nrow = wn * 32 + tp * 16 + (lane & 7) + 8 * (lane >> 4);
            const int kcol = ks * 16 + 8 * ((lane >> 3) & 1);
            ldsm4(bh, sb + SM_W3 + nrow * 272 + kcol * 2);
            #pragma unroll
            for (int tm = 0; tm < 2; ++tm) {
                mma_f16(acc3[tm][2*tp    ], afr[tm], &bh[0]);
                mma_f16(acc3[tm][2*tp + 1], afr[tm], &bh[2]);
            }
        }
    }

    // ============== layer3 epilogue + layer4 (registers + shfl) =============
    float part[4] = {0.0f, 0.0f, 0.0f, 0.0f};
    #pragma unroll
    for (int tn = 0; tn < 4; ++tn) {
        const int n = wn * 32 + tn * 8 + (lane & 3) * 2;
        const float bn0 = b3s[n], bn1 = b3s[n + 1];
        const float w0 = W4s[n],  w1 = W4s[n + 1];
        #pragma unroll
        for (int tm = 0; tm < 2; ++tm) {
            #pragma unroll
            for (int rr = 0; rr < 2; ++rr) {
                part[tm*2 + rr] += frelu(acc3[tm][tn][2*rr    ] + bn0) * w0
                                 + frelu(acc3[tm][tn][2*rr + 1] + bn1) * w1;
            }
        }
    }
    #pragma unroll
    for (int i = 0; i < 4; ++i) {
        part[i] += __shfl_xor_sync(0xffffffffu, part[i], 1);
        part[i] += __shfl_xor_sync(0xffffffffu, part[i], 2);
    }
    if ((lane & 3) == 0) {
        #pragma unroll
        for (int tm = 0; tm < 2; ++tm)
            #pragma unroll
            for (int rr = 0; rr < 2; ++rr) {
                const int m = wm * 32 + tm * 16 + rr * 8 + (lane >> 2);
                red[wn * 128 + m] = part[tm*2 + rr];
            }
    }
    __syncthreads();
    if (tid < 128) {
        const float v = red[tid] + red[128 + tid] + b4[0];
        out[(q0 + tid) * NS + s_idx] = 1.0f / (1.0f + expf(-v));
    }
}

// ---------------------------------------------------------------------------
extern "C" void kernel_launch(void* const* d_in, const int* in_sizes, int n_in,
                              void* d_out, int out_size)
{
    const float* qf = (const float*)d_in[0];
    const float* sf = (const float*)d_in[1];
    // d_in[2] = support_y (unused)
    const float* W1 = (const float*)d_in[3];
    const float* b1 = (const float*)d_in[4];
    const float* W2 = (const float*)d_in[5];
    const float* b2 = (const float*)d_in[6];
    const float* W3 = (const float*)d_in[7];
    const float* b3 = (const float*)d_in[8];
    const float* W4 = (const float*)d_in[9];
    const float* b4 = (const float*)d_in[10];
    float* out = (float*)d_out;

    cudaFuncSetAttribute(relation_mma_kernel,
                         cudaFuncAttributeMaxDynamicSharedMemorySize, SMEM_TOTAL);
    cudaFuncSetAttribute(precompute_mma_kernel,
                         cudaFuncAttributeMaxDynamicSharedMemorySize, PRE_SMEM_TOTAL);

    prep_weights_kernel<<<640, 256>>>(W1, W2, W3);
    precompute_mma_kernel<<<dim3(10, 2), 256, PRE_SMEM_TOTAL>>>(qf, sf, b1);
    relation_mma_kernel<<<dim3(NS, NQ / TM), 256, SMEM_TOTAL>>>(b2, b3, W4, b4, out);
}